// round 3
// baseline (speedup 1.0000x reference)
#include <cuda_runtime.h>
#include <cstdint>

#define M_TOK 12608   // 64*197
#define CIN   768
#define CD    256
#define NE    8192
#define NSPLIT 4

// ---- device scratch (allocation-free per harness rules) ----
__device__ float g_zf[M_TOK * CD];        // compressed tokens [M, 256]
__device__ float g_enorm[NE];             // ||emb_e||^2
__device__ float g_cval[NSPLIT * M_TOK];  // per-split best distance
__device__ int   g_cidx[NSPLIT * M_TOK];  // per-split best index
__device__ int   g_idx[M_TOK];            // final argmin
__device__ float g_lpart[M_TOK / 64];     // loss partials (197)

// ===================== ||e||^2 : one warp per codebook row =====================
__global__ void k_enorm(const float* __restrict__ E) {
    int w = threadIdx.x >> 5, lane = threadIdx.x & 31;
    int row = blockIdx.x * 8 + w;
    float s = 0.f;
#pragma unroll
    for (int t = 0; t < CD / 32; t++) {
        float v = E[(size_t)row * CD + lane + t * 32];
        s += v * v;
    }
#pragma unroll
    for (int off = 16; off > 0; off >>= 1) s += __shfl_down_sync(0xffffffffu, s, off);
    if (lane == 0) g_enorm[row] = s;
}

// ===================== compress GEMM: g_zf = z @ Wc + bc =====================
// 64x64 tile, BK=16, 256 threads, 4x4 microtile
__global__ void k_compress(const float* __restrict__ Z, const float* __restrict__ W,
                           const float* __restrict__ bias) {
    __shared__ float As[16][64];
    __shared__ float Bs[16][64];
    int tid = threadIdx.x;
    int tx = tid & 15, ty = tid >> 4;
    int row0 = blockIdx.y * 64, col0 = blockIdx.x * 64;
    int alr = tid >> 2, alc = (tid & 3) * 4;   // A: 64 rows x 16 k
    int blr = tid >> 4, blc = (tid & 15) * 4;  // B: 16 k x 64 cols
    float acc[4][4] = {};
    for (int kk = 0; kk < CIN; kk += 16) {
        float4 a = *(const float4*)&Z[(size_t)(row0 + alr) * CIN + kk + alc];
        As[alc + 0][alr] = a.x; As[alc + 1][alr] = a.y;
        As[alc + 2][alr] = a.z; As[alc + 3][alr] = a.w;
        float4 b = *(const float4*)&W[(size_t)(kk + blr) * CD + col0 + blc];
        *(float4*)&Bs[blr][blc] = b;
        __syncthreads();
#pragma unroll
        for (int k = 0; k < 16; k++) {
            float4 av = *(float4*)&As[k][ty * 4];
            float4 bv = *(float4*)&Bs[k][tx * 4];
            float ar[4] = {av.x, av.y, av.z, av.w};
            float br[4] = {bv.x, bv.y, bv.z, bv.w};
#pragma unroll
            for (int i = 0; i < 4; i++)
#pragma unroll
                for (int j = 0; j < 4; j++) acc[i][j] += ar[i] * br[j];
        }
        __syncthreads();
    }
    float4 bb = *(const float4*)&bias[col0 + tx * 4];
#pragma unroll
    for (int i = 0; i < 4; i++) {
        float4 o = {acc[i][0] + bb.x, acc[i][1] + bb.y, acc[i][2] + bb.z, acc[i][3] + bb.w};
        *(float4*)&g_zf[(size_t)(row0 + ty * 4 + i) * CD + col0 + tx * 4] = o;
    }
}

// ===================== distance + argmin =====================
// block = 64 tokens x 2048 codes (split blockIdx.y), tiles of 128 codes, K=256
// microtile 4 tokens x 8 codes per thread; running min, first-index ties.
__global__ void k_argmin(const float* __restrict__ E) {
    __shared__ float As[16][64];
    __shared__ float Es[16][128];
    __shared__ float redv[64][17];
    __shared__ int   redi[64][17];
    int tid = threadIdx.x, tx = tid & 15, ty = tid >> 4;
    int row0 = blockIdx.x * 64;
    int codeBase = blockIdx.y * (NE / NSPLIT);
    int alr = tid >> 2, alc = (tid & 3) * 4;
    float bestv[4]; int besti[4];
#pragma unroll
    for (int i = 0; i < 4; i++) { bestv[i] = 3.4e38f; besti[i] = 0; }

    for (int t = 0; t < NE / NSPLIT; t += 128) {
        int c0 = codeBase + t;
        float acc[4][8] = {};
        for (int kk = 0; kk < CD; kk += 16) {
            float4 a = *(const float4*)&g_zf[(size_t)(row0 + alr) * CD + kk + alc];
            As[alc + 0][alr] = a.x; As[alc + 1][alr] = a.y;
            As[alc + 2][alr] = a.z; As[alc + 3][alr] = a.w;
#pragma unroll
            for (int h = 0; h < 2; h++) {
                int er = alr + 64 * h;
                float4 e = *(const float4*)&E[(size_t)(c0 + er) * CD + kk + alc];
                Es[alc + 0][er] = e.x; Es[alc + 1][er] = e.y;
                Es[alc + 2][er] = e.z; Es[alc + 3][er] = e.w;
            }
            __syncthreads();
#pragma unroll
            for (int k = 0; k < 16; k++) {
                float4 av  = *(float4*)&As[k][ty * 4];
                float4 bv0 = *(float4*)&Es[k][tx * 8];
                float4 bv1 = *(float4*)&Es[k][tx * 8 + 4];
                float ar[4] = {av.x, av.y, av.z, av.w};
                float br[8] = {bv0.x, bv0.y, bv0.z, bv0.w, bv1.x, bv1.y, bv1.z, bv1.w};
#pragma unroll
                for (int i = 0; i < 4; i++)
#pragma unroll
                    for (int j = 0; j < 8; j++) acc[i][j] += ar[i] * br[j];
            }
            __syncthreads();
        }
#pragma unroll
        for (int j = 0; j < 8; j++) {
            int c = c0 + tx * 8 + j;
            float en = __ldg(&g_enorm[c]);
#pragma unroll
            for (int i = 0; i < 4; i++) {
                float d = en - 2.0f * acc[i][j];
                if (d < bestv[i]) { bestv[i] = d; besti[i] = c; }  // strict: keeps lowest idx
            }
        }
    }
#pragma unroll
    for (int i = 0; i < 4; i++) { redv[ty * 4 + i][tx] = bestv[i]; redi[ty * 4 + i][tx] = besti[i]; }
    __syncthreads();
    if (tid < 64) {
        float bv = redv[tid][0]; int bi = redi[tid][0];
#pragma unroll
        for (int t = 1; t < 16; t++) {
            float v = redv[tid][t]; int ii = redi[tid][t];
            if (v < bv || (v == bv && ii < bi)) { bv = v; bi = ii; }
        }
        g_cval[blockIdx.y * M_TOK + row0 + tid] = bv;
        g_cidx[blockIdx.y * M_TOK + row0 + tid] = bi;
    }
}

// ===================== reduce over splits =====================
__global__ void k_pick() {
    int m = blockIdx.x * blockDim.x + threadIdx.x;
    if (m >= M_TOK) return;
    float bv = g_cval[m]; int bi = g_cidx[m];
#pragma unroll
    for (int s = 1; s < NSPLIT; s++) {
        float v = g_cval[s * M_TOK + m]; int ii = g_cidx[s * M_TOK + m];
        if (v < bv || (v == bv && ii < bi)) { bv = v; bi = ii; }
    }
    g_idx[m] = bi;
}

// ===================== expand GEMM: out = emb[idx] @ We + be =====================
__global__ void k_expand(const float* __restrict__ E, const float* __restrict__ W,
                         const float* __restrict__ bias, float* __restrict__ out) {
    __shared__ float As[16][64];
    __shared__ float Bs[16][64];
    __shared__ int   idxS[64];
    int tid = threadIdx.x, tx = tid & 15, ty = tid >> 4;
    int row0 = blockIdx.y * 64, col0 = blockIdx.x * 64;
    if (tid < 64) idxS[tid] = g_idx[row0 + tid];
    __syncthreads();
    int alr = tid >> 2, alc = (tid & 3) * 4;
    int blr = tid >> 4, blc = (tid & 15) * 4;
    int arow = idxS[alr];
    float acc[4][4] = {};
    for (int kk = 0; kk < CD; kk += 16) {
        float4 a = *(const float4*)&E[(size_t)arow * CD + kk + alc];
        As[alc + 0][alr] = a.x; As[alc + 1][alr] = a.y;
        As[alc + 2][alr] = a.z; As[alc + 3][alr] = a.w;
        float4 b = *(const float4*)&W[(size_t)(kk + blr) * CIN + col0 + blc];
        *(float4*)&Bs[blr][blc] = b;
        __syncthreads();
#pragma unroll
        for (int k = 0; k < 16; k++) {
            float4 av = *(float4*)&As[k][ty * 4];
            float4 bv = *(float4*)&Bs[k][tx * 4];
            float ar[4] = {av.x, av.y, av.z, av.w};
            float br[4] = {bv.x, bv.y, bv.z, bv.w};
#pragma unroll
            for (int i = 0; i < 4; i++)
#pragma unroll
                for (int j = 0; j < 4; j++) acc[i][j] += ar[i] * br[j];
        }
        __syncthreads();
    }
    float4 bb = *(const float4*)&bias[col0 + tx * 4];
#pragma unroll
    for (int i = 0; i < 4; i++) {
        float4 o = {acc[i][0] + bb.x, acc[i][1] + bb.y, acc[i][2] + bb.z, acc[i][3] + bb.w};
        *(float4*)&out[(size_t)(row0 + ty * 4 + i) * CIN + col0 + tx * 4] = o;
    }
}

// ===================== loss partials: sum (emb[idx[m]] - zf[m])^2 over 64-row blocks ====
__global__ void k_loss(const float* __restrict__ E) {
    __shared__ int idxS[64];
    __shared__ float red[256];
    int row0 = blockIdx.x * 64;
    if (threadIdx.x < 64) idxS[threadIdx.x] = g_idx[row0 + threadIdx.x];
    __syncthreads();
    float s = 0.f;
    for (int idx = threadIdx.x; idx < 64 * CD; idx += 256) {
        int r = idx >> 8, k = idx & 255;
        float d = E[(size_t)idxS[r] * CD + k] - g_zf[(size_t)(row0 + r) * CD + k];
        s += d * d;
    }
    red[threadIdx.x] = s;
    __syncthreads();
    for (int off = 128; off > 0; off >>= 1) {
        if (threadIdx.x < off) red[threadIdx.x] += red[threadIdx.x + off];
        __syncthreads();
    }
    if (threadIdx.x == 0) g_lpart[blockIdx.x] = red[0];
}

// ===================== final loss reduce =====================
__global__ void k_final(float* out_loss) {
    __shared__ float red[256];
    float s = (threadIdx.x < M_TOK / 64) ? g_lpart[threadIdx.x] : 0.f;
    red[threadIdx.x] = s;
    __syncthreads();
    for (int off = 128; off > 0; off >>= 1) {
        if (threadIdx.x < off) red[threadIdx.x] += red[threadIdx.x + off];
        __syncthreads();
    }
    // loss = mean((zq-zf)^2) + 2*mean((zq-zf)^2) = 3 * mean
    if (threadIdx.x == 0) out_loss[0] = 3.0f * red[0] / (float)((size_t)M_TOK * CD);
}

extern "C" void kernel_launch(void* const* d_in, const int* in_sizes, int n_in,
                              void* d_out, int out_size) {
    const float* z   = (const float*)d_in[0];
    const float* emb = (const float*)d_in[1];
    const float* Wc  = (const float*)d_in[2];
    const float* bc  = (const float*)d_in[3];
    const float* We  = (const float*)d_in[4];
    const float* be  = (const float*)d_in[5];
    float* out = (float*)d_out;

    k_enorm<<<NE / 8, 256>>>(emb);
    k_compress<<<dim3(CD / 64, M_TOK / 64), 256>>>(z, Wc, bc);
    k_argmin<<<dim3(M_TOK / 64, NSPLIT), 256>>>(emb);
    k_pick<<<(M_TOK + 255) / 256, 256>>>();
    k_expand<<<dim3(CIN / 64, M_TOK / 64), 256>>>(emb, We, be, out);
    k_loss<<<M_TOK / 64, 256>>>(emb);
    if (out_size > M_TOK * CIN) k_final<<<1, 256>>>(out + (size_t)M_TOK * CIN);
}

// round 6
// speedup vs baseline: 1.7315x; 1.7315x over previous
#include <cuda_runtime.h>
#include <cstdint>

#define M_TOK 12608   // 64*197
#define CIN   768
#define CD    256
#define NE    8192
#define NSPLIT 3

// ---- device scratch (allocation-free per harness rules) ----
__device__ float g_zf[M_TOK * CD];        // compressed tokens [M, 256]
__device__ float g_enorm[NE];             // ||emb_e||^2
__device__ float g_cval[NSPLIT * M_TOK];  // per-split best distance
__device__ int   g_cidx[NSPLIT * M_TOK];  // per-split best index
__device__ int   g_idx[M_TOK];            // final argmin
__device__ float g_lpart[M_TOK / 64];     // loss partials (197)

// ===================== ||e||^2 : one warp per codebook row =====================
__global__ void k_enorm(const float* __restrict__ E) {
    int w = threadIdx.x >> 5, lane = threadIdx.x & 31;
    int row = blockIdx.x * 8 + w;
    float s = 0.f;
#pragma unroll
    for (int t = 0; t < CD / 32; t++) {
        float v = E[(size_t)row * CD + lane + t * 32];
        s += v * v;
    }
#pragma unroll
    for (int off = 16; off > 0; off >>= 1) s += __shfl_down_sync(0xffffffffu, s, off);
    if (lane == 0) g_enorm[row] = s;
}

// ============================================================================
// Shared GEMM geometry: block tile = 64 rows x 256 cols, 256 threads,
// 8x8 microtile. Warp w = ty owns rows {ty*4+i, 32+ty*4+i}; lane tx owns
// cols {tx*4+j, 128+tx*4+j}. BK=8, register-staged double buffering.
// ============================================================================

// ===================== compress GEMM: g_zf = z @ Wc + bc  (K=768) ============
__global__ __launch_bounds__(256, 2) void k_compress(const float* __restrict__ Z,
                                                     const float* __restrict__ W,
                                                     const float* __restrict__ bias) {
    __shared__ float As[2][8][64];    // [k][token]
    __shared__ float Bs[2][8][256];   // [k][col]
    int tid = threadIdx.x, tx = tid & 31, ty = tid >> 5;
    int row0 = blockIdx.x * 64;
    int aTok = tid >> 1, aK = (tid & 1) * 4;          // tid<128 loads A
    int bK0 = tid >> 6, bC0 = (tid & 63) * 4;         // q=tid
    int bK1 = (tid + 256) >> 6, bC1 = ((tid + 256) & 63) * 4;

    float acc[8][8] = {};
    float4 aReg = {}, bReg0, bReg1;

    // prologue: load k-tile 0
    if (tid < 128) aReg = *(const float4*)&Z[(size_t)(row0 + aTok) * CIN + aK];
    bReg0 = *(const float4*)&W[(size_t)bK0 * CD + bC0];
    bReg1 = *(const float4*)&W[(size_t)bK1 * CD + bC1];
    if (tid < 128) {
        As[0][aK + 0][aTok] = aReg.x; As[0][aK + 1][aTok] = aReg.y;
        As[0][aK + 2][aTok] = aReg.z; As[0][aK + 3][aTok] = aReg.w;
    }
    *(float4*)&Bs[0][bK0][bC0] = bReg0;
    *(float4*)&Bs[0][bK1][bC1] = bReg1;
    __syncthreads();

    const int KT = CIN / 8;  // 96
    for (int kt = 0; kt < KT; kt++) {
        int cur = kt & 1, nxt = cur ^ 1;
        if (kt + 1 < KT) {
            int kk = (kt + 1) * 8;
            if (tid < 128) aReg = *(const float4*)&Z[(size_t)(row0 + aTok) * CIN + kk + aK];
            bReg0 = *(const float4*)&W[(size_t)(kk + bK0) * CD + bC0];
            bReg1 = *(const float4*)&W[(size_t)(kk + bK1) * CD + bC1];
        }
#pragma unroll
        for (int k = 0; k < 8; k++) {
            float4 a0 = *(float4*)&As[cur][k][ty * 4];
            float4 a1 = *(float4*)&As[cur][k][32 + ty * 4];
            float4 b0 = *(float4*)&Bs[cur][k][tx * 4];
            float4 b1 = *(float4*)&Bs[cur][k][128 + tx * 4];
            float ar[8] = {a0.x, a0.y, a0.z, a0.w, a1.x, a1.y, a1.z, a1.w};
            float br[8] = {b0.x, b0.y, b0.z, b0.w, b1.x, b1.y, b1.z, b1.w};
#pragma unroll
            for (int i = 0; i < 8; i++)
#pragma unroll
                for (int j = 0; j < 8; j++) acc[i][j] = fmaf(ar[i], br[j], acc[i][j]);
        }
        if (kt + 1 < KT) {
            if (tid < 128) {
                As[nxt][aK + 0][aTok] = aReg.x; As[nxt][aK + 1][aTok] = aReg.y;
                As[nxt][aK + 2][aTok] = aReg.z; As[nxt][aK + 3][aTok] = aReg.w;
            }
            *(float4*)&Bs[nxt][bK0][bC0] = bReg0;
            *(float4*)&Bs[nxt][bK1][bC1] = bReg1;
        }
        __syncthreads();
    }

    float4 bb0 = *(const float4*)&bias[tx * 4];
    float4 bb1 = *(const float4*)&bias[128 + tx * 4];
#pragma unroll
    for (int i = 0; i < 8; i++) {
        int row = row0 + ((i < 4) ? ty * 4 + i : 32 + ty * 4 + (i - 4));
        float4 o0 = {acc[i][0] + bb0.x, acc[i][1] + bb0.y, acc[i][2] + bb0.z, acc[i][3] + bb0.w};
        float4 o1 = {acc[i][4] + bb1.x, acc[i][5] + bb1.y, acc[i][6] + bb1.z, acc[i][7] + bb1.w};
        *(float4*)&g_zf[(size_t)row * CD + tx * 4] = o0;
        *(float4*)&g_zf[(size_t)row * CD + 128 + tx * 4] = o1;
    }
}

// ===================== distance + argmin  (K=256, codes split 3-way) =========
// blockIdx.x = token tile (197), blockIdx.y = code split (3).
// Split s covers code tiles [t0, t1) of 256 codes: {0..10},{11..21},{22..31}.
__global__ __launch_bounds__(256, 2) void k_argmin(const float* __restrict__ E) {
    __shared__ float As[2][8][64];
    __shared__ float Es[2][8][256];
    int tid = threadIdx.x, tx = tid & 31, ty = tid >> 5;
    int row0 = blockIdx.x * 64;
    int s = blockIdx.y;
    int t0 = s * 11, t1 = (s == 2) ? 32 : t0 + 11;

    int aTok = tid >> 1, aK = (tid & 1) * 4;
    int eC0 = tid >> 1, eK0 = (tid & 1) * 4;
    int eC1 = (tid + 256) >> 1, eK1 = ((tid + 256) & 1) * 4;

    float bestv[8]; int besti[8];
#pragma unroll
    for (int i = 0; i < 8; i++) { bestv[i] = 3.4e38f; besti[i] = 0; }

    for (int tt = t0; tt < t1; tt++) {
        int c0 = tt * 256;
        float acc[8][8] = {};
        float4 aReg = {}, eReg0, eReg1;

        if (tid < 128) aReg = *(const float4*)&g_zf[(size_t)(row0 + aTok) * CD + aK];
        eReg0 = *(const float4*)&E[(size_t)(c0 + eC0) * CD + eK0];
        eReg1 = *(const float4*)&E[(size_t)(c0 + eC1) * CD + eK1];
        if (tid < 128) {
            As[0][aK + 0][aTok] = aReg.x; As[0][aK + 1][aTok] = aReg.y;
            As[0][aK + 2][aTok] = aReg.z; As[0][aK + 3][aTok] = aReg.w;
        }
        Es[0][eK0 + 0][eC0] = eReg0.x; Es[0][eK0 + 1][eC0] = eReg0.y;
        Es[0][eK0 + 2][eC0] = eReg0.z; Es[0][eK0 + 3][eC0] = eReg0.w;
        Es[0][eK1 + 0][eC1] = eReg1.x; Es[0][eK1 + 1][eC1] = eReg1.y;
        Es[0][eK1 + 2][eC1] = eReg1.z; Es[0][eK1 + 3][eC1] = eReg1.w;
        __syncthreads();

        const int KT = CD / 8;  // 32
        for (int kt = 0; kt < KT; kt++) {
            int cur = kt & 1, nxt = cur ^ 1;
            if (kt + 1 < KT) {
                int kk = (kt + 1) * 8;
                if (tid < 128) aReg = *(const float4*)&g_zf[(size_t)(row0 + aTok) * CD + kk + aK];
                eReg0 = *(const float4*)&E[(size_t)(c0 + eC0) * CD + kk + eK0];
                eReg1 = *(const float4*)&E[(size_t)(c0 + eC1) * CD + kk + eK1];
            }
#pragma unroll
            for (int k = 0; k < 8; k++) {
                float4 a0 = *(float4*)&As[cur][k][ty * 4];
                float4 a1 = *(float4*)&As[cur][k][32 + ty * 4];
                float4 b0 = *(float4*)&Es[cur][k][tx * 4];
                float4 b1 = *(float4*)&Es[cur][k][128 + tx * 4];
                float ar[8] = {a0.x, a0.y, a0.z, a0.w, a1.x, a1.y, a1.z, a1.w};
                float br[8] = {b0.x, b0.y, b0.z, b0.w, b1.x, b1.y, b1.z, b1.w};
#pragma unroll
                for (int i = 0; i < 8; i++)
#pragma unroll
                    for (int j = 0; j < 8; j++) acc[i][j] = fmaf(ar[i], br[j], acc[i][j]);
            }
            if (kt + 1 < KT) {
                if (tid < 128) {
                    As[nxt][aK + 0][aTok] = aReg.x; As[nxt][aK + 1][aTok] = aReg.y;
                    As[nxt][aK + 2][aTok] = aReg.z; As[nxt][aK + 3][aTok] = aReg.w;
                }
                Es[nxt][eK0 + 0][eC0] = eReg0.x; Es[nxt][eK0 + 1][eC0] = eReg0.y;
                Es[nxt][eK0 + 2][eC0] = eReg0.z; Es[nxt][eK0 + 3][eC0] = eReg0.w;
                Es[nxt][eK1 + 0][eC1] = eReg1.x; Es[nxt][eK1 + 1][eC1] = eReg1.y;
                Es[nxt][eK1 + 2][eC1] = eReg1.z; Es[nxt][eK1 + 3][eC1] = eReg1.w;
            }
            __syncthreads();
        }

        // d = ||e||^2 - 2 z.e ; codes visited in ascending order -> strict <
        // keeps the lowest index on ties.
#pragma unroll
        for (int j = 0; j < 8; j++) {
            int c = c0 + ((j < 4) ? tx * 4 + j : 128 + tx * 4 + (j - 4));
            float en = __ldg(&g_enorm[c]);
#pragma unroll
            for (int i = 0; i < 8; i++) {
                float d = en - 2.0f * acc[i][j];
                if (d < bestv[i]) { bestv[i] = d; besti[i] = c; }
            }
        }
    }

    // warp-level argmin reduce (each warp owns 8 token rows)
#pragma unroll
    for (int i = 0; i < 8; i++) {
        float v = bestv[i]; int bi = besti[i];
#pragma unroll
        for (int off = 16; off > 0; off >>= 1) {
            float ov = __shfl_xor_sync(0xffffffffu, v, off);
            int   oi = __shfl_xor_sync(0xffffffffu, bi, off);
            if (ov < v || (ov == v && oi < bi)) { v = ov; bi = oi; }
        }
        if (tx == 0) {
            int tok = row0 + ((i < 4) ? ty * 4 + i : 32 + ty * 4 + (i - 4));
            g_cval[s * M_TOK + tok] = v;
            g_cidx[s * M_TOK + tok] = bi;
        }
    }
}

// ===================== reduce over splits =====================
__global__ void k_pick() {
    int m = blockIdx.x * blockDim.x + threadIdx.x;
    if (m >= M_TOK) return;
    float bv = g_cval[m]; int bi = g_cidx[m];
#pragma unroll
    for (int s = 1; s < NSPLIT; s++) {
        float v = g_cval[s * M_TOK + m]; int ii = g_cidx[s * M_TOK + m];
        if (v < bv || (v == bv && ii < bi)) { bv = v; bi = ii; }
    }
    g_idx[m] = bi;
}

// ===================== expand GEMM: out = emb[idx] @ We + be  (K=256) ========
__global__ __launch_bounds__(256, 2) void k_expand(const float* __restrict__ E,
                                                   const float* __restrict__ W,
                                                   const float* __restrict__ bias,
                                                   float* __restrict__ out) {
    __shared__ float As[2][8][64];
    __shared__ float Bs[2][8][256];
    __shared__ int idxS[64];
    int tid = threadIdx.x, tx = tid & 31, ty = tid >> 5;
    int row0 = blockIdx.y * 64, col0 = blockIdx.x * 256;
    if (tid < 64) idxS[tid] = g_idx[row0 + tid];
    __syncthreads();

    int aTok = tid >> 1, aK = (tid & 1) * 4;
    size_t aBase = (tid < 128) ? (size_t)idxS[aTok] * CD : 0;
    int bK0 = tid >> 6, bC0 = (tid & 63) * 4;
    int bK1 = (tid + 256) >> 6, bC1 = ((tid + 256) & 63) * 4;

    float acc[8][8] = {};
    float4 aReg = {}, bReg0, bReg1;

    if (tid < 128) aReg = *(const float4*)&E[aBase + aK];
    bReg0 = *(const float4*)&W[(size_t)bK0 * CIN + col0 + bC0];
    bReg1 = *(const float4*)&W[(size_t)bK1 * CIN + col0 + bC1];
    if (tid < 128) {
        As[0][aK + 0][aTok] = aReg.x; As[0][aK + 1][aTok] = aReg.y;
        As[0][aK + 2][aTok] = aReg.z; As[0][aK + 3][aTok] = aReg.w;
    }
    *(float4*)&Bs[0][bK0][bC0] = bReg0;
    *(float4*)&Bs[0][bK1][bC1] = bReg1;
    __syncthreads();

    const int KT = CD / 8;  // 32
    for (int kt = 0; kt < KT; kt++) {
        int cur = kt & 1, nxt = cur ^ 1;
        if (kt + 1 < KT) {
            int kk = (kt + 1) * 8;
            if (tid < 128) aReg = *(const float4*)&E[aBase + kk + aK];
            bReg0 = *(const float4*)&W[(size_t)(kk + bK0) * CIN + col0 + bC0];
            bReg1 = *(const float4*)&W[(size_t)(kk + bK1) * CIN + col0 + bC1];
        }
#pragma unroll
        for (int k = 0; k < 8; k++) {
            float4 a0 = *(float4*)&As[cur][k][ty * 4];
            float4 a1 = *(float4*)&As[cur][k][32 + ty * 4];
            float4 b0 = *(float4*)&Bs[cur][k][tx * 4];
            float4 b1 = *(float4*)&Bs[cur][k][128 + tx * 4];
            float ar[8] = {a0.x, a0.y, a0.z, a0.w, a1.x, a1.y, a1.z, a1.w};
            float br[8] = {b0.x, b0.y, b0.z, b0.w, b1.x, b1.y, b1.z, b1.w};
#pragma unroll
            for (int i = 0; i < 8; i++)
#pragma unroll
                for (int j = 0; j < 8; j++) acc[i][j] = fmaf(ar[i], br[j], acc[i][j]);
        }
        if (kt + 1 < KT) {
            if (tid < 128) {
                As[nxt][aK + 0][aTok] = aReg.x; As[nxt][aK + 1][aTok] = aReg.y;
                As[nxt][aK + 2][aTok] = aReg.z; As[nxt][aK + 3][aTok] = aReg.w;
            }
            *(float4*)&Bs[nxt][bK0][bC0] = bReg0;
            *(float4*)&Bs[nxt][bK1][bC1] = bReg1;
        }
        __syncthreads();
    }

    float4 bb0 = *(const float4*)&bias[col0 + tx * 4];
    float4 bb1 = *(const float4*)&bias[col0 + 128 + tx * 4];
#pragma unroll
    for (int i = 0; i < 8; i++) {
        int row = row0 + ((i < 4) ? ty * 4 + i : 32 + ty * 4 + (i - 4));
        float4 o0 = {acc[i][0] + bb0.x, acc[i][1] + bb0.y, acc[i][2] + bb0.z, acc[i][3] + bb0.w};
        float4 o1 = {acc[i][4] + bb1.x, acc[i][5] + bb1.y, acc[i][6] + bb1.z, acc[i][7] + bb1.w};
        *(float4*)&out[(size_t)row * CIN + col0 + tx * 4] = o0;
        *(float4*)&out[(size_t)row * CIN + col0 + 128 + tx * 4] = o1;
    }
}

// ===================== loss partials =====================
__global__ void k_loss(const float* __restrict__ E) {
    __shared__ int idxS[64];
    __shared__ float red[256];
    int row0 = blockIdx.x * 64;
    if (threadIdx.x < 64) idxS[threadIdx.x] = g_idx[row0 + threadIdx.x];
    __syncthreads();
    float s = 0.f;
    for (int idx = threadIdx.x; idx < 64 * CD; idx += 256) {
        int r = idx >> 8, k = idx & 255;
        float d = E[(size_t)idxS[r] * CD + k] - g_zf[(size_t)(row0 + r) * CD + k];
        s += d * d;
    }
    red[threadIdx.x] = s;
    __syncthreads();
    for (int off = 128; off > 0; off >>= 1) {
        if (threadIdx.x < off) red[threadIdx.x] += red[threadIdx.x + off];
        __syncthreads();
    }
    if (threadIdx.x == 0) g_lpart[blockIdx.x] = red[0];
}

// ===================== final loss reduce =====================
__global__ void k_final(float* out_loss) {
    __shared__ float red[256];
    float s = (threadIdx.x < M_TOK / 64) ? g_lpart[threadIdx.x] : 0.f;
    red[threadIdx.x] = s;
    __syncthreads();
    for (int off = 128; off > 0; off >>= 1) {
        if (threadIdx.x < off) red[threadIdx.x] += red[threadIdx.x + off];
        __syncthreads();
    }
    if (threadIdx.x == 0) out_loss[0] = 3.0f * red[0] / (float)((size_t)M_TOK * CD);
}

extern "C" void kernel_launch(void* const* d_in, const int* in_sizes, int n_in,
                              void* d_out, int out_size) {
    const float* z   = (const float*)d_in[0];
    const float* emb = (const float*)d_in[1];
    const float* Wc  = (const float*)d_in[2];
    const float* bc  = (const float*)d_in[3];
    const float* We  = (const float*)d_in[4];
    const float* be  = (const float*)d_in[5];
    float* out = (float*)d_out;

    k_enorm<<<NE / 8, 256>>>(emb);
    k_compress<<<M_TOK / 64, 256>>>(z, Wc, bc);
    k_argmin<<<dim3(M_TOK / 64, NSPLIT), 256>>>(emb);
    k_pick<<<(M_TOK + 255) / 256, 256>>>();
    k_expand<<<dim3(CIN / 256, M_TOK / 64), 256>>>(emb, We, be, out);
    k_loss<<<M_TOK / 64, 256>>>(emb);
    if (out_size > M_TOK * CIN) k_final<<<1, 256>>>(out + (size_t)M_TOK * CIN);
}

// round 9
// speedup vs baseline: 3.4865x; 2.0136x over previous
#include <cuda_runtime.h>
#include <cuda_fp16.h>
#include <cstdint>

#define M_TOK 12608   // 64*197
#define M_PAD 12672   // 99*128
#define CIN   768
#define CD    256
#define NE    8192
#define NS    32      // code tiles (8192/256) -> partial argmin slots
#define NUNIT (99*32) // token tiles * code tiles

// ---- device scratch (allocation-free per harness rules) ----
__device__ float g_zf[M_TOK * CD];
__device__ float g_enorm[NE];
__device__ __half g_Ah[(size_t)M_PAD * 512];  // [zh(256) | zm(256)] per token
__device__ __half g_Eh[(size_t)NE * 512];     // [eh(256) | em(256)] per code
__device__ float g_cval[NS * M_TOK];
__device__ int   g_cidx[NS * M_TOK];
__device__ int   g_idx[M_TOK];
__device__ float g_lpart[M_TOK / 64];

// ======================= PTX helpers ========================================
__device__ __forceinline__ uint32_t smem_u32(const void* p) {
    uint32_t a;
    asm("{ .reg .u64 t; cvta.to.shared.u64 t, %1; cvt.u32.u64 %0, t; }" : "=r"(a) : "l"(p));
    return a;
}
#define CPASYNC16(dst, src) asm volatile("cp.async.cg.shared.global [%0], [%1], 16;" :: "r"(dst), "l"(src) : "memory")
#define CPCOMMIT() asm volatile("cp.async.commit_group;" ::: "memory")
#define CPWAIT1()  asm volatile("cp.async.wait_group 1;" ::: "memory")
#define CPWAIT0()  asm volatile("cp.async.wait_group 0;" ::: "memory")

__device__ __forceinline__ void ldsm_x4(uint32_t& r0, uint32_t& r1, uint32_t& r2,
                                        uint32_t& r3, uint32_t addr) {
    asm volatile("ldmatrix.sync.aligned.m8n8.x4.shared.b16 {%0,%1,%2,%3}, [%4];"
                 : "=r"(r0), "=r"(r1), "=r"(r2), "=r"(r3) : "r"(addr));
}
__device__ __forceinline__ void mma16816(float* c, const uint32_t* a, const uint32_t* b) {
    asm volatile(
        "mma.sync.aligned.m16n8k16.row.col.f32.f16.f16.f32 "
        "{%0,%1,%2,%3}, {%4,%5,%6,%7}, {%8,%9}, {%0,%1,%2,%3};"
        : "+f"(c[0]), "+f"(c[1]), "+f"(c[2]), "+f"(c[3])
        : "r"(a[0]), "r"(a[1]), "r"(a[2]), "r"(a[3]), "r"(b[0]), "r"(b[1]));
}

// ===================== ||e||^2 ==============================================
__global__ void k_enorm(const float* __restrict__ E) {
    int w = threadIdx.x >> 5, lane = threadIdx.x & 31;
    int row = blockIdx.x * 8 + w;
    float s = 0.f;
#pragma unroll
    for (int t = 0; t < CD / 32; t++) {
        float v = E[(size_t)row * CD + lane + t * 32];
        s += v * v;
    }
#pragma unroll
    for (int off = 16; off > 0; off >>= 1) s += __shfl_down_sync(0xffffffffu, s, off);
    if (lane == 0) g_enorm[row] = s;
}

// ===================== compress GEMM: g_zf = z @ Wc + bc  (K=768) ============
__global__ __launch_bounds__(256, 2) void k_compress(const float* __restrict__ Z,
                                                     const float* __restrict__ W,
                                                     const float* __restrict__ bias) {
    __shared__ float As[2][8][64];
    __shared__ float Bs[2][8][256];
    int tid = threadIdx.x, tx = tid & 31, ty = tid >> 5;
    int row0 = blockIdx.x * 64;
    int aTok = tid >> 1, aK = (tid & 1) * 4;
    int bK0 = tid >> 6, bC0 = (tid & 63) * 4;
    int bK1 = (tid + 256) >> 6, bC1 = ((tid + 256) & 63) * 4;

    float acc[8][8] = {};
    float4 aReg = {}, bReg0, bReg1;

    if (tid < 128) aReg = *(const float4*)&Z[(size_t)(row0 + aTok) * CIN + aK];
    bReg0 = *(const float4*)&W[(size_t)bK0 * CD + bC0];
    bReg1 = *(const float4*)&W[(size_t)bK1 * CD + bC1];
    if (tid < 128) {
        As[0][aK + 0][aTok] = aReg.x; As[0][aK + 1][aTok] = aReg.y;
        As[0][aK + 2][aTok] = aReg.z; As[0][aK + 3][aTok] = aReg.w;
    }
    *(float4*)&Bs[0][bK0][bC0] = bReg0;
    *(float4*)&Bs[0][bK1][bC1] = bReg1;
    __syncthreads();

    const int KT = CIN / 8;
    for (int kt = 0; kt < KT; kt++) {
        int cur = kt & 1, nxt = cur ^ 1;
        if (kt + 1 < KT) {
            int kk = (kt + 1) * 8;
            if (tid < 128) aReg = *(const float4*)&Z[(size_t)(row0 + aTok) * CIN + kk + aK];
            bReg0 = *(const float4*)&W[(size_t)(kk + bK0) * CD + bC0];
            bReg1 = *(const float4*)&W[(size_t)(kk + bK1) * CD + bC1];
        }
#pragma unroll
        for (int k = 0; k < 8; k++) {
            float4 a0 = *(float4*)&As[cur][k][ty * 4];
            float4 a1 = *(float4*)&As[cur][k][32 + ty * 4];
            float4 b0 = *(float4*)&Bs[cur][k][tx * 4];
            float4 b1 = *(float4*)&Bs[cur][k][128 + tx * 4];
            float ar[8] = {a0.x, a0.y, a0.z, a0.w, a1.x, a1.y, a1.z, a1.w};
            float br[8] = {b0.x, b0.y, b0.z, b0.w, b1.x, b1.y, b1.z, b1.w};
#pragma unroll
            for (int i = 0; i < 8; i++)
#pragma unroll
                for (int j = 0; j < 8; j++) acc[i][j] = fmaf(ar[i], br[j], acc[i][j]);
        }
        if (kt + 1 < KT) {
            if (tid < 128) {
                As[nxt][aK + 0][aTok] = aReg.x; As[nxt][aK + 1][aTok] = aReg.y;
                As[nxt][aK + 2][aTok] = aReg.z; As[nxt][aK + 3][aTok] = aReg.w;
            }
            *(float4*)&Bs[nxt][bK0][bC0] = bReg0;
            *(float4*)&Bs[nxt][bK1][bC1] = bReg1;
        }
        __syncthreads();
    }

    float4 bb0 = *(const float4*)&bias[tx * 4];
    float4 bb1 = *(const float4*)&bias[128 + tx * 4];
#pragma unroll
    for (int i = 0; i < 8; i++) {
        int row = row0 + ((i < 4) ? ty * 4 + i : 32 + ty * 4 + (i - 4));
        float4 o0 = {acc[i][0] + bb0.x, acc[i][1] + bb0.y, acc[i][2] + bb0.z, acc[i][3] + bb0.w};
        float4 o1 = {acc[i][4] + bb1.x, acc[i][5] + bb1.y, acc[i][6] + bb1.z, acc[i][7] + bb1.w};
        *(float4*)&g_zf[(size_t)row * CD + tx * 4] = o0;
        *(float4*)&g_zf[(size_t)row * CD + 128 + tx * 4] = o1;
    }
}

// ===================== fp16 2-way splits ====================================
__global__ void k_splitZ() {
    int row = blockIdx.x, c = threadIdx.x;
    float v = (row < M_TOK) ? g_zf[(size_t)row * CD + c] : 0.f;
    __half h = __float2half_rn(v);
    float r = v - __half2float(h);
    __half m = __float2half_rn(r);
    size_t b = (size_t)row * 512;
    g_Ah[b + c] = h; g_Ah[b + 256 + c] = m;
}
__global__ void k_splitE(const float* __restrict__ E) {
    int row = blockIdx.x, c = threadIdx.x;
    float v = E[(size_t)row * CD + c];
    __half h = __float2half_rn(v);
    float r = v - __half2float(h);
    __half m = __float2half_rn(r);
    size_t b = (size_t)row * 512;
    g_Eh[b + c] = h; g_Eh[b + 256 + c] = m;
}

// ===================== HMMA distance + argmin ===============================
// Persistent grid=148, 512 threads (16 warps, 4x4 warp grid). Work unit =
// (token tile 128) x (code tile 256). K = 3 segments x 256 = 12 chunks of 64:
// A segs {zh, zm, zh}, B segs {eh, eh, em} -> zh*eh + zm*eh + zh*em.
// Warp (wm, wn): 32 tokens x 64 codes; per k16: 2 m-tiles x 8 n-tiles HMMA.
#define SMA(st)  ((st) * 16384)
#define SMB(st)  (32768 + (st) * 32768)
#define SM_SVAL  98304
#define SM_SIDX  100352
#define SMEM_DIST 102400

__device__ __forceinline__ void load_chunk(uint32_t sb, int tid,
                                           const __half* Abase, const __half* Bbase,
                                           int c, int st) {
    int seg = c >> 2, w = c & 3;
    int aoff = (seg == 1) ? 256 : 0;  // zh, zm, zh
    int boff = (seg == 2) ? 256 : 0;  // eh, eh, em
    aoff += w * 64; boff += w * 64;
#pragma unroll
    for (int t = 0; t < 2; t++) {  // A: 128 rows x 128B
        int uu = tid + t * 512;
        int row = uu >> 3, q8 = uu & 7;
        const void* src = Abase + (size_t)row * 512 + aoff + q8 * 8;
        int bo = row * 128 + q8 * 16;
        CPASYNC16(sb + SMA(st) + (uint32_t)(bo ^ ((row & 7) << 4)), src);
    }
#pragma unroll
    for (int t = 0; t < 4; t++) {  // B: 256 rows x 128B
        int uu = tid + t * 512;
        int row = uu >> 3, q8 = uu & 7;
        const void* src = Bbase + (size_t)row * 512 + boff + q8 * 8;
        int bo = row * 128 + q8 * 16;
        CPASYNC16(sb + SMB(st) + (uint32_t)(bo ^ ((row & 7) << 4)), src);
    }
    CPCOMMIT();
}

__global__ __launch_bounds__(512, 1) void k_dist() {
    extern __shared__ char sm[];
    uint32_t sb = smem_u32(sm);
    float* sval = (float*)(sm + SM_SVAL);
    int*   sidx = (int*)(sm + SM_SIDX);
    int tid = threadIdx.x, lane = tid & 31, wid = tid >> 5;
    int wm = wid >> 2, wn = wid & 3;
    int q = lane >> 3, rw = lane & 7;

    // per-lane ldmatrix bases (swizzle XOR = rw<<4; other row terms are mult of 8)
    uint32_t aRow = (uint32_t)((wm * 32 + ((q & 1) << 3) + rw) * 128);
    uint32_t aKq = (uint32_t)((q >> 1) << 4);
    uint32_t bRow = (uint32_t)((wn * 64 + ((q >> 1) << 3) + rw) * 128);
    uint32_t bKq = (uint32_t)((q & 1) << 4);
    uint32_t swz = (uint32_t)(rw << 4);

    for (int u = blockIdx.x; u < NUNIT; u += gridDim.x) {
        int ct = u & 31, tt = u >> 5;
        int tok0 = tt * 128, c0 = ct * 256;
        const __half* Abase = &g_Ah[(size_t)tok0 * 512];
        const __half* Bbase = &g_Eh[(size_t)c0 * 512];

        float acc[2][8][4];
#pragma unroll
        for (int mt = 0; mt < 2; mt++)
#pragma unroll
            for (int nt = 0; nt < 8; nt++)
#pragma unroll
                for (int e = 0; e < 4; e++) acc[mt][nt][e] = 0.f;

        load_chunk(sb, tid, Abase, Bbase, 0, 0);
        load_chunk(sb, tid, Abase, Bbase, 1, 1);

        for (int c = 0; c < 12; c++) {
            int st = c & 1;
            if (c < 11) CPWAIT1(); else CPWAIT0();
            __syncthreads();
#pragma unroll
            for (int ks = 0; ks < 4; ks++) {
                uint32_t a[2][4];
#pragma unroll
                for (int mt = 0; mt < 2; mt++)
                    ldsm_x4(a[mt][0], a[mt][1], a[mt][2], a[mt][3],
                            sb + SMA(st) + aRow + mt * 2048 + (((uint32_t)(ks * 32) + aKq) ^ swz));
                uint32_t b[8][2];
#pragma unroll
                for (int p = 0; p < 4; p++)
                    ldsm_x4(b[2 * p][0], b[2 * p][1], b[2 * p + 1][0], b[2 * p + 1][1],
                            sb + SMB(st) + bRow + p * 2048 + (((uint32_t)(ks * 32) + bKq) ^ swz));
#pragma unroll
                for (int mt = 0; mt < 2; mt++)
#pragma unroll
                    for (int nt = 0; nt < 8; nt++)
                        mma16816(acc[mt][nt], a[mt], b[nt]);
            }
            __syncthreads();
            if (c + 2 < 12) load_chunk(sb, tid, Abase, Bbase, c + 2, st);
        }

        // epilogue: d = ||e||^2 - 2 z.e ; strict < keeps lowest index (cols ascend)
        float bestv[2][2]; int besti[2][2];
#pragma unroll
        for (int mt = 0; mt < 2; mt++)
#pragma unroll
            for (int key = 0; key < 2; key++) { bestv[mt][key] = 3.4e38f; besti[mt][key] = 0; }
#pragma unroll
        for (int nt = 0; nt < 8; nt++) {
            int colb = c0 + wn * 64 + nt * 8 + 2 * (lane & 3);
            float en0 = __ldg(&g_enorm[colb]);
            float en1 = __ldg(&g_enorm[colb + 1]);
#pragma unroll
            for (int mt = 0; mt < 2; mt++) {
#pragma unroll
                for (int key = 0; key < 2; key++) {
                    float d0 = en0 - 2.0f * acc[mt][nt][key * 2 + 0];
                    if (d0 < bestv[mt][key]) { bestv[mt][key] = d0; besti[mt][key] = colb; }
                    float d1 = en1 - 2.0f * acc[mt][nt][key * 2 + 1];
                    if (d1 < bestv[mt][key]) { bestv[mt][key] = d1; besti[mt][key] = colb + 1; }
                }
            }
        }
        // reduce across the 4 lanes of each quad (same token row, different cols)
#pragma unroll
        for (int mt = 0; mt < 2; mt++)
#pragma unroll
            for (int key = 0; key < 2; key++) {
                float v = bestv[mt][key]; int bi = besti[mt][key];
#pragma unroll
                for (int off = 1; off <= 2; off <<= 1) {
                    float ov = __shfl_xor_sync(0xffffffffu, v, off);
                    int   oi = __shfl_xor_sync(0xffffffffu, bi, off);
                    if (ov < v || (ov == v && oi < bi)) { v = ov; bi = oi; }
                }
                if ((lane & 3) == 0) {
                    int rowL = wm * 32 + mt * 16 + key * 8 + (lane >> 2);
                    sval[wn * 128 + rowL] = v;
                    sidx[wn * 128 + rowL] = bi;
                }
            }
        __syncthreads();
        if (tid < 128) {
            float v = sval[tid]; int bi = sidx[tid];
#pragma unroll
            for (int w = 1; w < 4; w++) {
                float ov = sval[w * 128 + tid]; int oi = sidx[w * 128 + tid];
                if (ov < v || (ov == v && oi < bi)) { v = ov; bi = oi; }
            }
            int tok = tok0 + tid;
            if (tok < M_TOK) {
                g_cval[ct * M_TOK + tok] = v;
                g_cidx[ct * M_TOK + tok] = bi;
            }
        }
        __syncthreads();
    }
}

// ===================== reduce over code-tile partials ========================
__global__ void k_pick() {
    int m = blockIdx.x * blockDim.x + threadIdx.x;
    if (m >= M_TOK) return;
    float bv = g_cval[m]; int bi = g_cidx[m];
#pragma unroll
    for (int s = 1; s < NS; s++) {
        float v = g_cval[s * M_TOK + m]; int ii = g_cidx[s * M_TOK + m];
        if (v < bv || (v == bv && ii < bi)) { bv = v; bi = ii; }
    }
    g_idx[m] = bi;
}

// ===================== expand GEMM: out = emb[idx] @ We + be  (K=256) ========
__global__ __launch_bounds__(256, 2) void k_expand(const float* __restrict__ E,
                                                   const float* __restrict__ W,
                                                   const float* __restrict__ bias,
                                                   float* __restrict__ out) {
    __shared__ float As[2][8][64];
    __shared__ float Bs[2][8][256];
    __shared__ int idxS[64];
    int tid = threadIdx.x, tx = tid & 31, ty = tid >> 5;
    int row0 = blockIdx.y * 64, col0 = blockIdx.x * 256;
    if (tid < 64) idxS[tid] = g_idx[row0 + tid];
    __syncthreads();

    int aTok = tid >> 1, aK = (tid & 1) * 4;
    size_t aBase = (tid < 128) ? (size_t)idxS[aTok] * CD : 0;
    int bK0 = tid >> 6, bC0 = (tid & 63) * 4;
    int bK1 = (tid + 256) >> 6, bC1 = ((tid + 256) & 63) * 4;

    float acc[8][8] = {};
    float4 aReg = {}, bReg0, bReg1;

    if (tid < 128) aReg = *(const float4*)&E[aBase + aK];
    bReg0 = *(const float4*)&W[(size_t)bK0 * CIN + col0 + bC0];
    bReg1 = *(const float4*)&W[(size_t)bK1 * CIN + col0 + bC1];
    if (tid < 128) {
        As[0][aK + 0][aTok] = aReg.x; As[0][aK + 1][aTok] = aReg.y;
        As[0][aK + 2][aTok] = aReg.z; As[0][aK + 3][aTok] = aReg.w;
    }
    *(float4*)&Bs[0][bK0][bC0] = bReg0;
    *(float4*)&Bs[0][bK1][bC1] = bReg1;
    __syncthreads();

    const int KT = CD / 8;
    for (int kt = 0; kt < KT; kt++) {
        int cur = kt & 1, nxt = cur ^ 1;
        if (kt + 1 < KT) {
            int kk = (kt + 1) * 8;
            if (tid < 128) aReg = *(const float4*)&E[aBase + kk + aK];
            bReg0 = *(const float4*)&W[(size_t)(kk + bK0) * CIN + col0 + bC0];
            bReg1 = *(const float4*)&W[(size_t)(kk + bK1) * CIN + col0 + bC1];
        }
#pragma unroll
        for (int k = 0; k < 8; k++) {
            float4 a0 = *(float4*)&As[cur][k][ty * 4];
            float4 a1 = *(float4*)&As[cur][k][32 + ty * 4];
            float4 b0 = *(float4*)&Bs[cur][k][tx * 4];
            float4 b1 = *(float4*)&Bs[cur][k][128 + tx * 4];
            float ar[8] = {a0.x, a0.y, a0.z, a0.w, a1.x, a1.y, a1.z, a1.w};
            float br[8] = {b0.x, b0.y, b0.z, b0.w, b1.x, b1.y, b1.z, b1.w};
#pragma unroll
            for (int i = 0; i < 8; i++)
#pragma unroll
                for (int j = 0; j < 8; j++) acc[i][j] = fmaf(ar[i], br[j], acc[i][j]);
        }
        if (kt + 1 < KT) {
            if (tid < 128) {
                As[nxt][aK + 0][aTok] = aReg.x; As[nxt][aK + 1][aTok] = aReg.y;
                As[nxt][aK + 2][aTok] = aReg.z; As[nxt][aK + 3][aTok] = aReg.w;
            }
            *(float4*)&Bs[nxt][bK0][bC0] = bReg0;
            *(float4*)&Bs[nxt][bK1][bC1] = bReg1;
        }
        __syncthreads();
    }

    float4 bb0 = *(const float4*)&bias[col0 + tx * 4];
    float4 bb1 = *(const float4*)&bias[col0 + 128 + tx * 4];
#pragma unroll
    for (int i = 0; i < 8; i++) {
        int row = row0 + ((i < 4) ? ty * 4 + i : 32 + ty * 4 + (i - 4));
        float4 o0 = {acc[i][0] + bb0.x, acc[i][1] + bb0.y, acc[i][2] + bb0.z, acc[i][3] + bb0.w};
        float4 o1 = {acc[i][4] + bb1.x, acc[i][5] + bb1.y, acc[i][6] + bb1.z, acc[i][7] + bb1.w};
        *(float4*)&out[(size_t)row * CIN + col0 + tx * 4] = o0;
        *(float4*)&out[(size_t)row * CIN + col0 + 128 + tx * 4] = o1;
    }
}

// ===================== loss partials =====================
__global__ void k_loss(const float* __restrict__ E) {
    __shared__ int idxS[64];
    __shared__ float red[256];
    int row0 = blockIdx.x * 64;
    if (threadIdx.x < 64) idxS[threadIdx.x] = g_idx[row0 + threadIdx.x];
    __syncthreads();
    float s = 0.f;
    for (int idx = threadIdx.x; idx < 64 * CD; idx += 256) {
        int r = idx >> 8, k = idx & 255;
        float d = E[(size_t)idxS[r] * CD + k] - g_zf[(size_t)(row0 + r) * CD + k];
        s += d * d;
    }
    red[threadIdx.x] = s;
    __syncthreads();
    for (int off = 128; off > 0; off >>= 1) {
        if (threadIdx.x < off) red[threadIdx.x] += red[threadIdx.x + off];
        __syncthreads();
    }
    if (threadIdx.x == 0) g_lpart[blockIdx.x] = red[0];
}

__global__ void k_final(float* out_loss) {
    __shared__ float red[256];
    float s = (threadIdx.x < M_TOK / 64) ? g_lpart[threadIdx.x] : 0.f;
    red[threadIdx.x] = s;
    __syncthreads();
    for (int off = 128; off > 0; off >>= 1) {
        if (threadIdx.x < off) red[threadIdx.x] += red[threadIdx.x + off];
        __syncthreads();
    }
    if (threadIdx.x == 0) out_loss[0] = 3.0f * red[0] / (float)((size_t)M_TOK * CD);
}

extern "C" void kernel_launch(void* const* d_in, const int* in_sizes, int n_in,
                              void* d_out, int out_size) {
    const float* z   = (const float*)d_in[0];
    const float* emb = (const float*)d_in[1];
    const float* Wc  = (const float*)d_in[2];
    const float* bc  = (const float*)d_in[3];
    const float* We  = (const float*)d_in[4];
    const float* be  = (const float*)d_in[5];
    float* out = (float*)d_out;

    cudaFuncSetAttribute(k_dist, cudaFuncAttributeMaxDynamicSharedMemorySize, SMEM_DIST);

    k_enorm<<<NE / 8, 256>>>(emb);
    k_splitE<<<NE, 256>>>(emb);
    k_compress<<<M_TOK / 64, 256>>>(z, Wc, bc);
    k_splitZ<<<M_PAD, 256>>>();
    k_dist<<<148, 512, SMEM_DIST>>>();
    k_pick<<<(M_TOK + 255) / 256, 256>>>();
    k_expand<<<dim3(CIN / 256, M_TOK / 64), 256>>>(emb, We, be, out);
    k_loss<<<M_TOK / 64, 256>>>(emb);
    if (out_size > M_TOK * CIN) k_final<<<1, 256>>>(out + (size_t)M_TOK * CIN);
}

// round 10
// speedup vs baseline: 3.9619x; 1.1363x over previous
#include <cuda_runtime.h>
#include <cuda_fp16.h>
#include <cstdint>

#define M_TOK 12608   // 64*197
#define M_PAD 12672   // 99*128
#define CIN   768
#define CD    256
#define NE    8192
#define NS    32      // code tiles (8192/256) -> partial argmin slots
#define NUNIT (99*32) // token tiles * code tiles
#define NUEXP (99*3)  // token tiles * n tiles (768/256)

// ---- device scratch (allocation-free per harness rules) ----
__device__ float g_zf[M_TOK * CD];
__device__ float g_enorm[NE];
__device__ __half g_Ah[(size_t)M_PAD * 512];  // [zh(256) | zm(256)] per token (pad rows stay 0)
__device__ __half g_Eh[(size_t)NE * 512];     // [eh(256) | em(256)] per code
__device__ __half g_Wt[(size_t)CIN * 512];    // transposed We splits: [wh(256) | wm(256)] per n-row
__device__ float g_cval[NS * M_TOK];
__device__ int   g_cidx[NS * M_TOK];
__device__ int   g_idx[M_TOK];
__device__ float g_lpart[M_TOK / 64];

// ======================= PTX helpers ========================================
__device__ __forceinline__ uint32_t smem_u32(const void* p) {
    uint32_t a;
    asm("{ .reg .u64 t; cvta.to.shared.u64 t, %1; cvt.u32.u64 %0, t; }" : "=r"(a) : "l"(p));
    return a;
}
#define CPASYNC16(dst, src) asm volatile("cp.async.cg.shared.global [%0], [%1], 16;" :: "r"(dst), "l"(src) : "memory")
#define CPCOMMIT() asm volatile("cp.async.commit_group;" ::: "memory")
#define CPWAIT1()  asm volatile("cp.async.wait_group 1;" ::: "memory")
#define CPWAIT0()  asm volatile("cp.async.wait_group 0;" ::: "memory")

__device__ __forceinline__ void ldsm_x4(uint32_t& r0, uint32_t& r1, uint32_t& r2,
                                        uint32_t& r3, uint32_t addr) {
    asm volatile("ldmatrix.sync.aligned.m8n8.x4.shared.b16 {%0,%1,%2,%3}, [%4];"
                 : "=r"(r0), "=r"(r1), "=r"(r2), "=r"(r3) : "r"(addr));
}
__device__ __forceinline__ void mma16816(float* c, const uint32_t* a, const uint32_t* b) {
    asm volatile(
        "mma.sync.aligned.m16n8k16.row.col.f32.f16.f16.f32 "
        "{%0,%1,%2,%3}, {%4,%5,%6,%7}, {%8,%9}, {%0,%1,%2,%3};"
        : "+f"(c[0]), "+f"(c[1]), "+f"(c[2]), "+f"(c[3])
        : "r"(a[0]), "r"(a[1]), "r"(a[2]), "r"(a[3]), "r"(b[0]), "r"(b[1]));
}

// ===================== prep E: ||e||^2 + fp16 2-way split ===================
__global__ void k_prepE(const float* __restrict__ E) {
    __shared__ float red[8];
    int row = blockIdx.x, c = threadIdx.x;
    float v = E[(size_t)row * CD + c];
    __half h = __float2half_rn(v);
    float r = v - __half2float(h);
    __half m = __float2half_rn(r);
    size_t b = (size_t)row * 512;
    g_Eh[b + c] = h; g_Eh[b + 256 + c] = m;
    float s = v * v;
#pragma unroll
    for (int off = 16; off > 0; off >>= 1) s += __shfl_down_sync(0xffffffffu, s, off);
    if ((c & 31) == 0) red[c >> 5] = s;
    __syncthreads();
    if (c == 0) {
        float t = 0.f;
#pragma unroll
        for (int w = 0; w < 8; w++) t += red[w];
        g_enorm[row] = t;
    }
}

// ===================== transpose + split We -> g_Wt ========================
// We is [CD=256 k][CIN=768 n]; g_Wt[n][0:256]=wh(k), [256:512]=wm(k)
__global__ void k_splitWt(const float* __restrict__ We) {
    __shared__ float t[32][33];
    int k0 = blockIdx.x * 32, n0 = blockIdx.y * 32;
    int tx = threadIdx.x, ty = threadIdx.y;  // 32 x 8
#pragma unroll
    for (int r = 0; r < 32; r += 8)
        t[ty + r][tx] = We[(size_t)(k0 + ty + r) * CIN + n0 + tx];
    __syncthreads();
#pragma unroll
    for (int r = 0; r < 32; r += 8) {
        int n = n0 + ty + r, k = k0 + tx;
        float v = t[tx][ty + r];
        __half h = __float2half_rn(v);
        __half m = __float2half_rn(v - __half2float(h));
        g_Wt[(size_t)n * 512 + k] = h;
        g_Wt[(size_t)n * 512 + 256 + k] = m;
    }
}

// ===================== compress GEMM + fused zf split =======================
__global__ __launch_bounds__(256, 2) void k_compress(const float* __restrict__ Z,
                                                     const float* __restrict__ W,
                                                     const float* __restrict__ bias) {
    __shared__ float As[2][8][64];
    __shared__ float Bs[2][8][256];
    int tid = threadIdx.x, tx = tid & 31, ty = tid >> 5;
    int row0 = blockIdx.x * 64;
    int aTok = tid >> 1, aK = (tid & 1) * 4;
    int bK0 = tid >> 6, bC0 = (tid & 63) * 4;
    int bK1 = (tid + 256) >> 6, bC1 = ((tid + 256) & 63) * 4;

    float acc[8][8] = {};
    float4 aReg = {}, bReg0, bReg1;

    if (tid < 128) aReg = *(const float4*)&Z[(size_t)(row0 + aTok) * CIN + aK];
    bReg0 = *(const float4*)&W[(size_t)bK0 * CD + bC0];
    bReg1 = *(const float4*)&W[(size_t)bK1 * CD + bC1];
    if (tid < 128) {
        As[0][aK + 0][aTok] = aReg.x; As[0][aK + 1][aTok] = aReg.y;
        As[0][aK + 2][aTok] = aReg.z; As[0][aK + 3][aTok] = aReg.w;
    }
    *(float4*)&Bs[0][bK0][bC0] = bReg0;
    *(float4*)&Bs[0][bK1][bC1] = bReg1;
    __syncthreads();

    const int KT = CIN / 8;
    for (int kt = 0; kt < KT; kt++) {
        int cur = kt & 1, nxt = cur ^ 1;
        if (kt + 1 < KT) {
            int kk = (kt + 1) * 8;
            if (tid < 128) aReg = *(const float4*)&Z[(size_t)(row0 + aTok) * CIN + kk + aK];
            bReg0 = *(const float4*)&W[(size_t)(kk + bK0) * CD + bC0];
            bReg1 = *(const float4*)&W[(size_t)(kk + bK1) * CD + bC1];
        }
#pragma unroll
        for (int k = 0; k < 8; k++) {
            float4 a0 = *(float4*)&As[cur][k][ty * 4];
            float4 a1 = *(float4*)&As[cur][k][32 + ty * 4];
            float4 b0 = *(float4*)&Bs[cur][k][tx * 4];
            float4 b1 = *(float4*)&Bs[cur][k][128 + tx * 4];
            float ar[8] = {a0.x, a0.y, a0.z, a0.w, a1.x, a1.y, a1.z, a1.w};
            float br[8] = {b0.x, b0.y, b0.z, b0.w, b1.x, b1.y, b1.z, b1.w};
#pragma unroll
            for (int i = 0; i < 8; i++)
#pragma unroll
                for (int j = 0; j < 8; j++) acc[i][j] = fmaf(ar[i], br[j], acc[i][j]);
        }
        if (kt + 1 < KT) {
            if (tid < 128) {
                As[nxt][aK + 0][aTok] = aReg.x; As[nxt][aK + 1][aTok] = aReg.y;
                As[nxt][aK + 2][aTok] = aReg.z; As[nxt][aK + 3][aTok] = aReg.w;
            }
            *(float4*)&Bs[nxt][bK0][bC0] = bReg0;
            *(float4*)&Bs[nxt][bK1][bC1] = bReg1;
        }
        __syncthreads();
    }

    float4 bb0 = *(const float4*)&bias[tx * 4];
    float4 bb1 = *(const float4*)&bias[128 + tx * 4];
#pragma unroll
    for (int i = 0; i < 8; i++) {
        int row = row0 + ((i < 4) ? ty * 4 + i : 32 + ty * 4 + (i - 4));
        float o[8] = {acc[i][0] + bb0.x, acc[i][1] + bb0.y, acc[i][2] + bb0.z, acc[i][3] + bb0.w,
                      acc[i][4] + bb1.x, acc[i][5] + bb1.y, acc[i][6] + bb1.z, acc[i][7] + bb1.w};
        *(float4*)&g_zf[(size_t)row * CD + tx * 4] = *(float4*)&o[0];
        *(float4*)&g_zf[(size_t)row * CD + 128 + tx * 4] = *(float4*)&o[4];
        // fused fp16 2-way split
        size_t zb = (size_t)row * 512;
#pragma unroll
        for (int half_ = 0; half_ < 2; half_++) {
            int cbase = half_ * 128 + tx * 4;
            __half h[4], m[4];
#pragma unroll
            for (int j = 0; j < 4; j++) {
                float v = o[half_ * 4 + j];
                h[j] = __float2half_rn(v);
                m[j] = __float2half_rn(v - __half2float(h[j]));
            }
            *(__half2*)&g_Ah[zb + cbase]       = __halves2half2(h[0], h[1]);
            *(__half2*)&g_Ah[zb + cbase + 2]   = __halves2half2(h[2], h[3]);
            *(__half2*)&g_Ah[zb + 256 + cbase]     = __halves2half2(m[0], m[1]);
            *(__half2*)&g_Ah[zb + 256 + cbase + 2] = __halves2half2(m[2], m[3]);
        }
    }
}

// ===================== HMMA distance + argmin (3-stage) =====================
// Persistent grid=148, 512 threads (16 warps, 4x4). Unit = 128 tok x 256 codes.
// K = 3 segs x 256 = 12 chunks of 64: A {zh,zm,zh}, B {eh,eh,em}.
#define DS_STAGE 49152
#define DSA(st) ((st) * DS_STAGE)
#define DSB(st) ((st) * DS_STAGE + 16384)
#define DS_SVAL 147456
#define DS_SIDX 149504
#define SMEM_DIST 151552

__device__ __forceinline__ void dist_load(uint32_t sb, int tid,
                                          const __half* Abase, const __half* Bbase,
                                          int c, int st) {
    int seg = c >> 2, w = c & 3;
    int aoff = ((seg == 1) ? 256 : 0) + w * 64;  // zh, zm, zh
    int boff = ((seg == 2) ? 256 : 0) + w * 64;  // eh, eh, em
#pragma unroll
    for (int t = 0; t < 2; t++) {  // A: 128 rows x 128B
        int uu = tid + t * 512;
        int row = uu >> 3, q8 = uu & 7;
        const void* src = Abase + (size_t)row * 512 + aoff + q8 * 8;
        int bo = row * 128 + q8 * 16;
        CPASYNC16(sb + DSA(st) + (uint32_t)(bo ^ ((row & 7) << 4)), src);
    }
#pragma unroll
    for (int t = 0; t < 4; t++) {  // B: 256 rows x 128B
        int uu = tid + t * 512;
        int row = uu >> 3, q8 = uu & 7;
        const void* src = Bbase + (size_t)row * 512 + boff + q8 * 8;
        int bo = row * 128 + q8 * 16;
        CPASYNC16(sb + DSB(st) + (uint32_t)(bo ^ ((row & 7) << 4)), src);
    }
    CPCOMMIT();
}

__global__ __launch_bounds__(512, 1) void k_dist() {
    extern __shared__ char sm[];
    uint32_t sb = smem_u32(sm);
    float* sval = (float*)(sm + DS_SVAL);
    int*   sidx = (int*)(sm + DS_SIDX);
    int tid = threadIdx.x, lane = tid & 31, wid = tid >> 5;
    int wm = wid >> 2, wn = wid & 3;
    int q = lane >> 3, rw = lane & 7;

    uint32_t aRow = (uint32_t)((wm * 32 + ((q & 1) << 3) + rw) * 128);
    uint32_t aKq = (uint32_t)((q >> 1) << 4);
    uint32_t bRow = (uint32_t)((wn * 64 + ((q >> 1) << 3) + rw) * 128);
    uint32_t bKq = (uint32_t)((q & 1) << 4);
    uint32_t swz = (uint32_t)(rw << 4);

    for (int u = blockIdx.x; u < NUNIT; u += gridDim.x) {
        int ct = u & 31, tt = u >> 5;
        int tok0 = tt * 128, c0 = ct * 256;
        const __half* Abase = &g_Ah[(size_t)tok0 * 512];
        const __half* Bbase = &g_Eh[(size_t)c0 * 512];

        float acc[2][8][4];
#pragma unroll
        for (int mt = 0; mt < 2; mt++)
#pragma unroll
            for (int nt = 0; nt < 8; nt++)
#pragma unroll
                for (int e = 0; e < 4; e++) acc[mt][nt][e] = 0.f;

        dist_load(sb, tid, Abase, Bbase, 0, 0);
        dist_load(sb, tid, Abase, Bbase, 1, 1);

        int st = 0;
        for (int c = 0; c < 12; c++) {
            if (c < 11) CPWAIT1(); else CPWAIT0();
            __syncthreads();
            if (c + 2 < 12) {
                int st2 = st + 2; if (st2 >= 3) st2 -= 3;
                dist_load(sb, tid, Abase, Bbase, c + 2, st2);
            }
#pragma unroll
            for (int ks = 0; ks < 4; ks++) {
                uint32_t a[2][4];
#pragma unroll
                for (int mt = 0; mt < 2; mt++)
                    ldsm_x4(a[mt][0], a[mt][1], a[mt][2], a[mt][3],
                            sb + DSA(st) + aRow + mt * 2048 + (((uint32_t)(ks * 32) + aKq) ^ swz));
                uint32_t b[8][2];
#pragma unroll
                for (int p = 0; p < 4; p++)
                    ldsm_x4(b[2 * p][0], b[2 * p][1], b[2 * p + 1][0], b[2 * p + 1][1],
                            sb + DSB(st) + bRow + p * 2048 + (((uint32_t)(ks * 32) + bKq) ^ swz));
#pragma unroll
                for (int mt = 0; mt < 2; mt++)
#pragma unroll
                    for (int nt = 0; nt < 8; nt++)
                        mma16816(acc[mt][nt], a[mt], b[nt]);
            }
            if (++st >= 3) st = 0;
        }

        // epilogue: d = ||e||^2 - 2 z.e ; strict < keeps lowest index
        float bestv[2][2]; int besti[2][2];
#pragma unroll
        for (int mt = 0; mt < 2; mt++)
#pragma unroll
            for (int key = 0; key < 2; key++) { bestv[mt][key] = 3.4e38f; besti[mt][key] = 0; }
#pragma unroll
        for (int nt = 0; nt < 8; nt++) {
            int colb = c0 + wn * 64 + nt * 8 + 2 * (lane & 3);
            float en0 = __ldg(&g_enorm[colb]);
            float en1 = __ldg(&g_enorm[colb + 1]);
#pragma unroll
            for (int mt = 0; mt < 2; mt++) {
#pragma unroll
                for (int key = 0; key < 2; key++) {
                    float d0 = en0 - 2.0f * acc[mt][nt][key * 2 + 0];
                    if (d0 < bestv[mt][key]) { bestv[mt][key] = d0; besti[mt][key] = colb; }
                    float d1 = en1 - 2.0f * acc[mt][nt][key * 2 + 1];
                    if (d1 < bestv[mt][key]) { bestv[mt][key] = d1; besti[mt][key] = colb + 1; }
                }
            }
        }
#pragma unroll
        for (int mt = 0; mt < 2; mt++)
#pragma unroll
            for (int key = 0; key < 2; key++) {
                float v = bestv[mt][key]; int bi = besti[mt][key];
#pragma unroll
                for (int off = 1; off <= 2; off <<= 1) {
                    float ov = __shfl_xor_sync(0xffffffffu, v, off);
                    int   oi = __shfl_xor_sync(0xffffffffu, bi, off);
                    if (ov < v || (ov == v && oi < bi)) { v = ov; bi = oi; }
                }
                if ((lane & 3) == 0) {
                    int rowL = wm * 32 + mt * 16 + key * 8 + (lane >> 2);
                    sval[wn * 128 + rowL] = v;
                    sidx[wn * 128 + rowL] = bi;
                }
            }
        __syncthreads();
        if (tid < 128) {
            float v = sval[tid]; int bi = sidx[tid];
#pragma unroll
            for (int w = 1; w < 4; w++) {
                float ov = sval[w * 128 + tid]; int oi = sidx[w * 128 + tid];
                if (ov < v || (ov == v && oi < bi)) { v = ov; bi = oi; }
            }
            int tok = tok0 + tid;
            if (tok < M_TOK) {
                g_cval[ct * M_TOK + tok] = v;
                g_cidx[ct * M_TOK + tok] = bi;
            }
        }
        __syncthreads();
    }
}

// ===================== reduce over code-tile partials ========================
__global__ void k_pick() {
    int m = blockIdx.x * blockDim.x + threadIdx.x;
    if (m >= M_TOK) return;
    float bv = g_cval[m]; int bi = g_cidx[m];
#pragma unroll
    for (int s = 1; s < NS; s++) {
        float v = g_cval[s * M_TOK + m]; int ii = g_cidx[s * M_TOK + m];
        if (v < bv || (v == bv && ii < bi)) { bv = v; bi = ii; }
    }
    g_idx[m] = bi;
}

// ===================== HMMA expand: out = emb[idx] @ We + be ================
// Unit = 128 tokens x 256 out-cols. K = 3 segs x 256 = 12 chunks of 64:
// A {eh, em, eh} (gathered rows of g_Eh), B {wh, wh, wm} (rows of g_Wt).
#define EX_IDX 147456
#define SMEM_EXP 147968

__global__ __launch_bounds__(512, 1) void k_expand(const float* __restrict__ bias,
                                                   float* __restrict__ out) {
    extern __shared__ char sm[];
    uint32_t sb = smem_u32(sm);
    int* idxS = (int*)(sm + EX_IDX);
    int tid = threadIdx.x, lane = tid & 31, wid = tid >> 5;
    int wm = wid >> 2, wn = wid & 3;
    int q = lane >> 3, rw = lane & 7;

    uint32_t aRow = (uint32_t)((wm * 32 + ((q & 1) << 3) + rw) * 128);
    uint32_t aKq = (uint32_t)((q >> 1) << 4);
    uint32_t bRow = (uint32_t)((wn * 64 + ((q >> 1) << 3) + rw) * 128);
    uint32_t bKq = (uint32_t)((q & 1) << 4);
    uint32_t swz = (uint32_t)(rw << 4);

    int u = blockIdx.x;
    int tt = u / 3, n3 = u - tt * 3;
    int tok0 = tt * 128, ncol0 = n3 * 256;

    if (tid < 128) {
        int tok = tok0 + tid;
        idxS[tid] = (tok < M_TOK) ? g_idx[tok] : 0;
    }
    __syncthreads();

    const __half* Bbase = &g_Wt[(size_t)ncol0 * 512];

    float acc[2][8][4];
#pragma unroll
    for (int mt = 0; mt < 2; mt++)
#pragma unroll
        for (int nt = 0; nt < 8; nt++)
#pragma unroll
            for (int e = 0; e < 4; e++) acc[mt][nt][e] = 0.f;

    // chunk loader (A gathered)
    auto load = [&](int c, int st) {
        int seg = c >> 2, w = c & 3;
        int aoff = ((seg == 1) ? 256 : 0) + w * 64;  // eh, em, eh
        int boff = ((seg == 2) ? 256 : 0) + w * 64;  // wh, wh, wm
#pragma unroll
        for (int t = 0; t < 2; t++) {
            int uu = tid + t * 512;
            int row = uu >> 3, q8 = uu & 7;
            const void* src = &g_Eh[(size_t)idxS[row] * 512 + aoff + q8 * 8];
            int bo = row * 128 + q8 * 16;
            CPASYNC16(sb + DSA(st) + (uint32_t)(bo ^ ((row & 7) << 4)), src);
        }
#pragma unroll
        for (int t = 0; t < 4; t++) {
            int uu = tid + t * 512;
            int row = uu >> 3, q8 = uu & 7;
            const void* src = Bbase + (size_t)row * 512 + boff + q8 * 8;
            int bo = row * 128 + q8 * 16;
            CPASYNC16(sb + DSB(st) + (uint32_t)(bo ^ ((row & 7) << 4)), src);
        }
        CPCOMMIT();
    };

    load(0, 0);
    load(1, 1);
    int st = 0;
    for (int c = 0; c < 12; c++) {
        if (c < 11) CPWAIT1(); else CPWAIT0();
        __syncthreads();
        if (c + 2 < 12) {
            int st2 = st + 2; if (st2 >= 3) st2 -= 3;
            load(c + 2, st2);
        }
#pragma unroll
        for (int ks = 0; ks < 4; ks++) {
            uint32_t a[2][4];
#pragma unroll
            for (int mt = 0; mt < 2; mt++)
                ldsm_x4(a[mt][0], a[mt][1], a[mt][2], a[mt][3],
                        sb + DSA(st) + aRow + mt * 2048 + (((uint32_t)(ks * 32) + aKq) ^ swz));
            uint32_t b[8][2];
#pragma unroll
            for (int p = 0; p < 4; p++)
                ldsm_x4(b[2 * p][0], b[2 * p][1], b[2 * p + 1][0], b[2 * p + 1][1],
                        sb + DSB(st) + bRow + p * 2048 + (((uint32_t)(ks * 32) + bKq) ^ swz));
#pragma unroll
            for (int mt = 0; mt < 2; mt++)
#pragma unroll
                for (int nt = 0; nt < 8; nt++)
                    mma16816(acc[mt][nt], a[mt], b[nt]);
        }
        if (++st >= 3) st = 0;
    }

    // epilogue: out[tok][col] = acc + be[col]
#pragma unroll
    for (int nt = 0; nt < 8; nt++) {
        int col = ncol0 + wn * 64 + nt * 8 + 2 * (lane & 3);
        float b0 = __ldg(&bias[col]), b1 = __ldg(&bias[col + 1]);
#pragma unroll
        for (int mt = 0; mt < 2; mt++) {
#pragma unroll
            for (int key = 0; key < 2; key++) {
                int tok = tok0 + wm * 32 + mt * 16 + key * 8 + (lane >> 2);
                if (tok < M_TOK) {
                    float2 o = {acc[mt][nt][key * 2 + 0] + b0, acc[mt][nt][key * 2 + 1] + b1};
                    *(float2*)&out[(size_t)tok * CIN + col] = o;
                }
            }
        }
    }
}

// ===================== loss partials =====================
__global__ void k_loss(const float* __restrict__ E) {
    __shared__ int idxS[64];
    __shared__ float red[256];
    int row0 = blockIdx.x * 64;
    if (threadIdx.x < 64) idxS[threadIdx.x] = g_idx[row0 + threadIdx.x];
    __syncthreads();
    float s = 0.f;
    for (int idx = threadIdx.x; idx < 64 * CD; idx += 256) {
        int r = idx >> 8, k = idx & 255;
        float d = E[(size_t)idxS[r] * CD + k] - g_zf[(size_t)(row0 + r) * CD + k];
        s += d * d;
    }
    red[threadIdx.x] = s;
    __syncthreads();
    for (int off = 128; off > 0; off >>= 1) {
        if (threadIdx.x < off) red[threadIdx.x] += red[threadIdx.x + off];
        __syncthreads();
    }
    if (threadIdx.x == 0) g_lpart[blockIdx.x] = red[0];
}

__global__ void k_final(float* out_loss) {
    __shared__ float red[256];
    float s = (threadIdx.x < M_TOK / 64) ? g_lpart[threadIdx.x] : 0.f;
    red[threadIdx.x] = s;
    __syncthreads();
    for (int off = 128; off > 0; off >>= 1) {
        if (threadIdx.x < off) red[threadIdx.x] += red[threadIdx.x + off];
        __syncthreads();
    }
    if (threadIdx.x == 0) out_loss[0] = 3.0f * red[0] / (float)((size_t)M_TOK * CD);
}

extern "C" void kernel_launch(void* const* d_in, const int* in_sizes, int n_in,
                              void* d_out, int out_size) {
    const float* z   = (const float*)d_in[0];
    const float* emb = (const float*)d_in[1];
    const float* Wc  = (const float*)d_in[2];
    const float* bc  = (const float*)d_in[3];
    const float* We  = (const float*)d_in[4];
    const float* be  = (const float*)d_in[5];
    float* out = (float*)d_out;

    cudaFuncSetAttribute(k_dist, cudaFuncAttributeMaxDynamicSharedMemorySize, SMEM_DIST);
    cudaFuncSetAttribute(k_expand, cudaFuncAttributeMaxDynamicSharedMemorySize, SMEM_EXP);

    k_prepE<<<NE, 256>>>(emb);
    k_splitWt<<<dim3(8, 24), dim3(32, 8)>>>(We);
    k_compress<<<M_TOK / 64, 256>>>(z, Wc, bc);
    k_dist<<<148, 512, SMEM_DIST>>>();
    k_pick<<<(M_TOK + 255) / 256, 256>>>();
    k_expand<<<NUEXP, 512, SMEM_EXP>>>(be, out);
    k_loss<<<M_TOK / 64, 256>>>(emb);
    if (out_size > M_TOK * CIN) k_final<<<1, 256>>>(out + (size_t)M_TOK * CIN);
}

// round 12
// speedup vs baseline: 4.1340x; 1.0434x over previous
#include <cuda_runtime.h>
#include <cuda_fp16.h>
#include <cstdint>

#define M_TOK 12608   // 64*197
#define M_PAD 12672   // 99*128
#define CIN   768
#define CD    256
#define NE    8192
#define NS    64      // code tiles (8192/128) -> partial argmin slots
#define NUNIT (99*64) // token tiles * code tiles
#define NUEXP (99*3)  // token tiles * n tiles (768/256)

// ---- device scratch (allocation-free per harness rules) ----
__device__ float g_zf[M_TOK * CD];
__device__ float g_enorm[NE];
__device__ __half g_Ah[(size_t)M_PAD * 512];  // [zh(256) | zm(256)] per token (pad rows stay 0)
__device__ __half g_Eh[(size_t)NE * 512];     // [eh(256) | em(256)] per code
__device__ __half g_Wt[(size_t)CIN * 512];    // transposed We splits: [wh(256) | wm(256)] per n-row
__device__ float g_cval[NS * M_TOK];
__device__ int   g_cidx[NS * M_TOK];
__device__ int   g_idx[M_TOK];
__device__ float g_lpart[M_TOK / 64];

// ======================= PTX helpers ========================================
__device__ __forceinline__ uint32_t smem_u32(const void* p) {
    uint32_t a;
    asm("{ .reg .u64 t; cvta.to.shared.u64 t, %1; cvt.u32.u64 %0, t; }" : "=r"(a) : "l"(p));
    return a;
}
#define CPASYNC16(dst, src) asm volatile("cp.async.cg.shared.global [%0], [%1], 16;" :: "r"(dst), "l"(src) : "memory")
#define CPCOMMIT() asm volatile("cp.async.commit_group;" ::: "memory")
#define CPWAIT1()  asm volatile("cp.async.wait_group 1;" ::: "memory")
#define CPWAIT0()  asm volatile("cp.async.wait_group 0;" ::: "memory")

__device__ __forceinline__ void ldsm_x4(uint32_t& r0, uint32_t& r1, uint32_t& r2,
                                        uint32_t& r3, uint32_t addr) {
    asm volatile("ldmatrix.sync.aligned.m8n8.x4.shared.b16 {%0,%1,%2,%3}, [%4];"
                 : "=r"(r0), "=r"(r1), "=r"(r2), "=r"(r3) : "r"(addr));
}
__device__ __forceinline__ void mma16816(float* c, const uint32_t* a, const uint32_t* b) {
    asm volatile(
        "mma.sync.aligned.m16n8k16.row.col.f32.f16.f16.f32 "
        "{%0,%1,%2,%3}, {%4,%5,%6,%7}, {%8,%9}, {%0,%1,%2,%3};"
        : "+f"(c[0]), "+f"(c[1]), "+f"(c[2]), "+f"(c[3])
        : "r"(a[0]), "r"(a[1]), "r"(a[2]), "r"(a[3]), "r"(b[0]), "r"(b[1]));
}

// ===================== prep E: ||e||^2 + fp16 2-way split ===================
__global__ void k_prepE(const float* __restrict__ E) {
    __shared__ float red[8];
    int row = blockIdx.x, c = threadIdx.x;
    float v = E[(size_t)row * CD + c];
    __half h = __float2half_rn(v);
    float r = v - __half2float(h);
    __half m = __float2half_rn(r);
    size_t b = (size_t)row * 512;
    g_Eh[b + c] = h; g_Eh[b + 256 + c] = m;
    float s = v * v;
#pragma unroll
    for (int off = 16; off > 0; off >>= 1) s += __shfl_down_sync(0xffffffffu, s, off);
    if ((c & 31) == 0) red[c >> 5] = s;
    __syncthreads();
    if (c == 0) {
        float t = 0.f;
#pragma unroll
        for (int w = 0; w < 8; w++) t += red[w];
        g_enorm[row] = t;
    }
}

// ===================== transpose + split We -> g_Wt ========================
__global__ void k_splitWt(const float* __restrict__ We) {
    __shared__ float t[32][33];
    int k0 = blockIdx.x * 32, n0 = blockIdx.y * 32;
    int tx = threadIdx.x, ty = threadIdx.y;  // 32 x 8
#pragma unroll
    for (int r = 0; r < 32; r += 8)
        t[ty + r][tx] = We[(size_t)(k0 + ty + r) * CIN + n0 + tx];
    __syncthreads();
#pragma unroll
    for (int r = 0; r < 32; r += 8) {
        int n = n0 + ty + r, k = k0 + tx;
        float v = t[tx][ty + r];
        __half h = __float2half_rn(v);
        __half m = __float2half_rn(v - __half2float(h));
        g_Wt[(size_t)n * 512 + k] = h;
        g_Wt[(size_t)n * 512 + 256 + k] = m;
    }
}

// ===================== compress GEMM + fused zf split =======================
__global__ __launch_bounds__(256, 2) void k_compress(const float* __restrict__ Z,
                                                     const float* __restrict__ W,
                                                     const float* __restrict__ bias) {
    __shared__ float As[2][8][64];
    __shared__ float Bs[2][8][256];
    int tid = threadIdx.x, tx = tid & 31, ty = tid >> 5;
    int row0 = blockIdx.x * 64;
    int aTok = tid >> 1, aK = (tid & 1) * 4;
    int bK0 = tid >> 6, bC0 = (tid & 63) * 4;
    int bK1 = (tid + 256) >> 6, bC1 = ((tid + 256) & 63) * 4;

    float acc[8][8] = {};
    float4 aReg = {}, bReg0, bReg1;

    if (tid < 128) aReg = *(const float4*)&Z[(size_t)(row0 + aTok) * CIN + aK];
    bReg0 = *(const float4*)&W[(size_t)bK0 * CD + bC0];
    bReg1 = *(const float4*)&W[(size_t)bK1 * CD + bC1];
    if (tid < 128) {
        As[0][aK + 0][aTok] = aReg.x; As[0][aK + 1][aTok] = aReg.y;
        As[0][aK + 2][aTok] = aReg.z; As[0][aK + 3][aTok] = aReg.w;
    }
    *(float4*)&Bs[0][bK0][bC0] = bReg0;
    *(float4*)&Bs[0][bK1][bC1] = bReg1;
    __syncthreads();

    const int KT = CIN / 8;
    for (int kt = 0; kt < KT; kt++) {
        int cur = kt & 1, nxt = cur ^ 1;
        if (kt + 1 < KT) {
            int kk = (kt + 1) * 8;
            if (tid < 128) aReg = *(const float4*)&Z[(size_t)(row0 + aTok) * CIN + kk + aK];
            bReg0 = *(const float4*)&W[(size_t)(kk + bK0) * CD + bC0];
            bReg1 = *(const float4*)&W[(size_t)(kk + bK1) * CD + bC1];
        }
#pragma unroll
        for (int k = 0; k < 8; k++) {
            float4 a0 = *(float4*)&As[cur][k][ty * 4];
            float4 a1 = *(float4*)&As[cur][k][32 + ty * 4];
            float4 b0 = *(float4*)&Bs[cur][k][tx * 4];
            float4 b1 = *(float4*)&Bs[cur][k][128 + tx * 4];
            float ar[8] = {a0.x, a0.y, a0.z, a0.w, a1.x, a1.y, a1.z, a1.w};
            float br[8] = {b0.x, b0.y, b0.z, b0.w, b1.x, b1.y, b1.z, b1.w};
#pragma unroll
            for (int i = 0; i < 8; i++)
#pragma unroll
                for (int j = 0; j < 8; j++) acc[i][j] = fmaf(ar[i], br[j], acc[i][j]);
        }
        if (kt + 1 < KT) {
            if (tid < 128) {
                As[nxt][aK + 0][aTok] = aReg.x; As[nxt][aK + 1][aTok] = aReg.y;
                As[nxt][aK + 2][aTok] = aReg.z; As[nxt][aK + 3][aTok] = aReg.w;
            }
            *(float4*)&Bs[nxt][bK0][bC0] = bReg0;
            *(float4*)&Bs[nxt][bK1][bC1] = bReg1;
        }
        __syncthreads();
    }

    float4 bb0 = *(const float4*)&bias[tx * 4];
    float4 bb1 = *(const float4*)&bias[128 + tx * 4];
#pragma unroll
    for (int i = 0; i < 8; i++) {
        int row = row0 + ((i < 4) ? ty * 4 + i : 32 + ty * 4 + (i - 4));
        float o[8] = {acc[i][0] + bb0.x, acc[i][1] + bb0.y, acc[i][2] + bb0.z, acc[i][3] + bb0.w,
                      acc[i][4] + bb1.x, acc[i][5] + bb1.y, acc[i][6] + bb1.z, acc[i][7] + bb1.w};
        *(float4*)&g_zf[(size_t)row * CD + tx * 4] = *(float4*)&o[0];
        *(float4*)&g_zf[(size_t)row * CD + 128 + tx * 4] = *(float4*)&o[4];
        size_t zb = (size_t)row * 512;
#pragma unroll
        for (int half_ = 0; half_ < 2; half_++) {
            int cbase = half_ * 128 + tx * 4;
            __half h[4], m[4];
#pragma unroll
            for (int j = 0; j < 4; j++) {
                float v = o[half_ * 4 + j];
                h[j] = __float2half_rn(v);
                m[j] = __float2half_rn(v - __half2float(h[j]));
            }
            *(__half2*)&g_Ah[zb + cbase]       = __halves2half2(h[0], h[1]);
            *(__half2*)&g_Ah[zb + cbase + 2]   = __halves2half2(h[2], h[3]);
            *(__half2*)&g_Ah[zb + 256 + cbase]     = __halves2half2(m[0], m[1]);
            *(__half2*)&g_Ah[zb + 256 + cbase + 2] = __halves2half2(m[2], m[3]);
        }
    }
}

// ===================== HMMA distance + argmin ===============================
// Persistent grid=296 (2 CTAs/SM), 256 threads (8 warps, 4m x 2n).
// Unit = 128 tokens x 128 codes. K = 3 segs x 256 = 12 chunks of 64:
// A {zh,zm,zh}, B {eh,eh,em}. 3-stage ring + cross-unit prefetch.
#define DS_STAGE 32768
#define DSA(st) ((st) * DS_STAGE)
#define DSB(st) ((st) * DS_STAGE + 16384)
#define DS_SVAL 98304
#define DS_SIDX 99328
#define SMEM_DIST 100352

__device__ __forceinline__ void dist_load(uint32_t sb, int tid,
                                          const __half* Abase, const __half* Bbase,
                                          int c, int st, bool valid) {
    if (valid) {
        int seg = c >> 2, w = c & 3;
        int aoff = ((seg == 1) ? 256 : 0) + w * 64;  // zh, zm, zh
        int boff = ((seg == 2) ? 256 : 0) + w * 64;  // eh, eh, em
#pragma unroll
        for (int t = 0; t < 4; t++) {  // A: 128 rows x 128B
            int uu = tid + t * 256;
            int row = uu >> 3, q8 = uu & 7;
            const void* src = Abase + (size_t)row * 512 + aoff + q8 * 8;
            int bo = row * 128 + q8 * 16;
            CPASYNC16(sb + DSA(st) + (uint32_t)(bo ^ ((row & 7) << 4)), src);
        }
#pragma unroll
        for (int t = 0; t < 4; t++) {  // B: 128 rows x 128B
            int uu = tid + t * 256;
            int row = uu >> 3, q8 = uu & 7;
            const void* src = Bbase + (size_t)row * 512 + boff + q8 * 8;
            int bo = row * 128 + q8 * 16;
            CPASYNC16(sb + DSB(st) + (uint32_t)(bo ^ ((row & 7) << 4)), src);
        }
    }
    CPCOMMIT();
}

__global__ __launch_bounds__(256, 2) void k_dist() {
    extern __shared__ char sm[];
    uint32_t sb = smem_u32(sm);
    float* sval = (float*)(sm + DS_SVAL);
    int*   sidx = (int*)(sm + DS_SIDX);
    int tid = threadIdx.x, lane = tid & 31, wid = tid >> 5;
    int wm = wid >> 1, wn = wid & 1;
    int q = lane >> 3, rw = lane & 7;

    uint32_t aRow = (uint32_t)((wm * 32 + ((q & 1) << 3) + rw) * 128);
    uint32_t aKq = (uint32_t)((q >> 1) << 4);
    uint32_t bRow = (uint32_t)((wn * 64 + ((q >> 1) << 3) + rw) * 128);
    uint32_t bKq = (uint32_t)((q & 1) << 4);
    uint32_t swz = (uint32_t)(rw << 4);

    int u = blockIdx.x;
    const __half* Ab = &g_Ah[(size_t)(u >> 6) * 128 * 512];
    const __half* Bb = &g_Eh[(size_t)(u & 63) * 128 * 512];
    int st = 0;
    dist_load(sb, tid, Ab, Bb, 0, 0, u < NUNIT);
    dist_load(sb, tid, Ab, Bb, 1, 1, u < NUNIT);

    for (; u < NUNIT; u += gridDim.x) {
        int tt = u >> 6, ct = u & 63;
        int tok0 = tt * 128, c0 = ct * 128;
        int un = u + gridDim.x;
        // pointer arithmetic only when un >= NUNIT (never dereferenced)
        const __half* Abn = &g_Ah[(size_t)(un >> 6) * 128 * 512];
        const __half* Bbn = &g_Eh[(size_t)(un & 63) * 128 * 512];

        float acc[2][8][4];
#pragma unroll
        for (int mt = 0; mt < 2; mt++)
#pragma unroll
            for (int nt = 0; nt < 8; nt++)
#pragma unroll
                for (int e = 0; e < 4; e++) acc[mt][nt][e] = 0.f;

        for (int c = 0; c < 12; c++) {
            CPWAIT1();
            __syncthreads();
            int st2 = st + 2; if (st2 >= 3) st2 -= 3;
            if (c < 10) dist_load(sb, tid, Ab, Bb, c + 2, st2, true);
            else        dist_load(sb, tid, Abn, Bbn, c - 10, st2, un < NUNIT);
#pragma unroll
            for (int ks = 0; ks < 4; ks++) {
                uint32_t a[2][4];
#pragma unroll
                for (int mt = 0; mt < 2; mt++)
                    ldsm_x4(a[mt][0], a[mt][1], a[mt][2], a[mt][3],
                            sb + DSA(st) + aRow + mt * 2048 + (((uint32_t)(ks * 32) + aKq) ^ swz));
                uint32_t b[8][2];
#pragma unroll
                for (int p = 0; p < 4; p++)
                    ldsm_x4(b[2 * p][0], b[2 * p][1], b[2 * p + 1][0], b[2 * p + 1][1],
                            sb + DSB(st) + bRow + p * 2048 + (((uint32_t)(ks * 32) + bKq) ^ swz));
#pragma unroll
                for (int mt = 0; mt < 2; mt++)
#pragma unroll
                    for (int nt = 0; nt < 8; nt++)
                        mma16816(acc[mt][nt], a[mt], b[nt]);
            }
            if (++st >= 3) st = 0;
        }

        // epilogue: d = ||e||^2 - 2 z.e ; strict < keeps lowest index
        float bestv[2][2]; int besti[2][2];
#pragma unroll
        for (int mt = 0; mt < 2; mt++)
#pragma unroll
            for (int key = 0; key < 2; key++) { bestv[mt][key] = 3.4e38f; besti[mt][key] = 0; }
#pragma unroll
        for (int nt = 0; nt < 8; nt++) {
            int colb = c0 + wn * 64 + nt * 8 + 2 * (lane & 3);
            float en0 = __ldg(&g_enorm[colb]);
            float en1 = __ldg(&g_enorm[colb + 1]);
#pragma unroll
            for (int mt = 0; mt < 2; mt++) {
#pragma unroll
                for (int key = 0; key < 2; key++) {
                    float d0 = en0 - 2.0f * acc[mt][nt][key * 2 + 0];
                    if (d0 < bestv[mt][key]) { bestv[mt][key] = d0; besti[mt][key] = colb; }
                    float d1 = en1 - 2.0f * acc[mt][nt][key * 2 + 1];
                    if (d1 < bestv[mt][key]) { bestv[mt][key] = d1; besti[mt][key] = colb + 1; }
                }
            }
        }
#pragma unroll
        for (int mt = 0; mt < 2; mt++)
#pragma unroll
            for (int key = 0; key < 2; key++) {
                float v = bestv[mt][key]; int bi = besti[mt][key];
#pragma unroll
                for (int off = 1; off <= 2; off <<= 1) {
                    float ov = __shfl_xor_sync(0xffffffffu, v, off);
                    int   oi = __shfl_xor_sync(0xffffffffu, bi, off);
                    if (ov < v || (ov == v && oi < bi)) { v = ov; bi = oi; }
                }
                if ((lane & 3) == 0) {
                    int rowL = wm * 32 + mt * 16 + key * 8 + (lane >> 2);
                    sval[wn * 128 + rowL] = v;
                    sidx[wn * 128 + rowL] = bi;
                }
            }
        __syncthreads();
        if (tid < 128) {
            float v = sval[tid]; int bi = sidx[tid];
            float ov = sval[128 + tid]; int oi = sidx[128 + tid];
            if (ov < v || (ov == v && oi < bi)) { v = ov; bi = oi; }
            int tok = tok0 + tid;
            if (tok < M_TOK) {
                g_cval[ct * M_TOK + tok] = v;
                g_cidx[ct * M_TOK + tok] = bi;
            }
        }
        __syncthreads();
        Ab = Abn; Bb = Bbn;
    }
}

// ===================== reduce over code-tile partials ========================
__global__ void k_pick() {
    int m = blockIdx.x * blockDim.x + threadIdx.x;
    if (m >= M_TOK) return;
    float bv = g_cval[m]; int bi = g_cidx[m];
#pragma unroll 8
    for (int s = 1; s < NS; s++) {
        float v = g_cval[s * M_TOK + m]; int ii = g_cidx[s * M_TOK + m];
        if (v < bv || (v == bv && ii < bi)) { bv = v; bi = ii; }
    }
    g_idx[m] = bi;
}

// ===================== HMMA expand: out = emb[idx] @ We + be ================
#define ES_STAGE 49152
#define ESA(st) ((st) * ES_STAGE)
#define ESB(st) ((st) * ES_STAGE + 16384)
#define EX_IDX 147456
#define SMEM_EXP 147968

__global__ __launch_bounds__(512, 1) void k_expand(const float* __restrict__ bias,
                                                   float* __restrict__ out) {
    extern __shared__ char sm[];
    uint32_t sb = smem_u32(sm);
    int* idxS = (int*)(sm + EX_IDX);
    int tid = threadIdx.x, lane = tid & 31, wid = tid >> 5;
    int wm = wid >> 2, wn = wid & 3;
    int q = lane >> 3, rw = lane & 7;

    uint32_t aRow = (uint32_t)((wm * 32 + ((q & 1) << 3) + rw) * 128);
    uint32_t aKq = (uint32_t)((q >> 1) << 4);
    uint32_t bRow = (uint32_t)((wn * 64 + ((q >> 1) << 3) + rw) * 128);
    uint32_t bKq = (uint32_t)((q & 1) << 4);
    uint32_t swz = (uint32_t)(rw << 4);

    int u = blockIdx.x;
    int tt = u / 3, n3 = u - tt * 3;
    int tok0 = tt * 128, ncol0 = n3 * 256;

    if (tid < 128) {
        int tok = tok0 + tid;
        idxS[tid] = (tok < M_TOK) ? g_idx[tok] : 0;
    }
    __syncthreads();

    const __half* Bbase = &g_Wt[(size_t)ncol0 * 512];

    float acc[2][8][4];
#pragma unroll
    for (int mt = 0; mt < 2; mt++)
#pragma unroll
        for (int nt = 0; nt < 8; nt++)
#pragma unroll
            for (int e = 0; e < 4; e++) acc[mt][nt][e] = 0.f;

    auto load = [&](int c, int st) {
        int seg = c >> 2, w = c & 3;
        int aoff = ((seg == 1) ? 256 : 0) + w * 64;  // eh, em, eh
        int boff = ((seg == 2) ? 256 : 0) + w * 64;  // wh, wh, wm
#pragma unroll
        for (int t = 0; t < 2; t++) {
            int uu = tid + t * 512;
            int row = uu >> 3, q8 = uu & 7;
            const void* src = &g_Eh[(size_t)idxS[row] * 512 + aoff + q8 * 8];
            int bo = row * 128 + q8 * 16;
            CPASYNC16(sb + ESA(st) + (uint32_t)(bo ^ ((row & 7) << 4)), src);
        }
#pragma unroll
        for (int t = 0; t < 4; t++) {
            int uu = tid + t * 512;
            int row = uu >> 3, q8 = uu & 7;
            const void* src = Bbase + (size_t)row * 512 + boff + q8 * 8;
            int bo = row * 128 + q8 * 16;
            CPASYNC16(sb + ESB(st) + (uint32_t)(bo ^ ((row & 7) << 4)), src);
        }
        CPCOMMIT();
    };

    load(0, 0);
    load(1, 1);
    int st = 0;
    for (int c = 0; c < 12; c++) {
        if (c < 11) CPWAIT1(); else CPWAIT0();
        __syncthreads();
        if (c + 2 < 12) {
            int st2 = st + 2; if (st2 >= 3) st2 -= 3;
            load(c + 2, st2);
        }
#pragma unroll
        for (int ks = 0; ks < 4; ks++) {
            uint32_t a[2][4];
#pragma unroll
            for (int mt = 0; mt < 2; mt++)
                ldsm_x4(a[mt][0], a[mt][1], a[mt][2], a[mt][3],
                        sb + ESA(st) + aRow + mt * 2048 + (((uint32_t)(ks * 32) + aKq) ^ swz));
            uint32_t b[8][2];
#pragma unroll
            for (int p = 0; p < 4; p++)
                ldsm_x4(b[2 * p][0], b[2 * p][1], b[2 * p + 1][0], b[2 * p + 1][1],
                        sb + ESB(st) + bRow + p * 2048 + (((uint32_t)(ks * 32) + bKq) ^ swz));
#pragma unroll
            for (int mt = 0; mt < 2; mt++)
#pragma unroll
                for (int nt = 0; nt < 8; nt++)
                    mma16816(acc[mt][nt], a[mt], b[nt]);
        }
        if (++st >= 3) st = 0;
    }

#pragma unroll
    for (int nt = 0; nt < 8; nt++) {
        int col = ncol0 + wn * 64 + nt * 8 + 2 * (lane & 3);
        float b0 = __ldg(&bias[col]), b1 = __ldg(&bias[col + 1]);
#pragma unroll
        for (int mt = 0; mt < 2; mt++) {
#pragma unroll
            for (int key = 0; key < 2; key++) {
                int tok = tok0 + wm * 32 + mt * 16 + key * 8 + (lane >> 2);
                if (tok < M_TOK) {
                    float2 o = {acc[mt][nt][key * 2 + 0] + b0, acc[mt][nt][key * 2 + 1] + b1};
                    *(float2*)&out[(size_t)tok * CIN + col] = o;
                }
            }
        }
    }
}

// ===================== loss partials =====================
__global__ void k_loss(const float* __restrict__ E) {
    __shared__ int idxS[64];
    __shared__ float red[256];
    int row0 = blockIdx.x * 64;
    if (threadIdx.x < 64) idxS[threadIdx.x] = g_idx[row0 + threadIdx.x];
    __syncthreads();
    float s = 0.f;
    for (int idx = threadIdx.x; idx < 64 * CD; idx += 256) {
        int r = idx >> 8, k = idx & 255;
        float d = E[(size_t)idxS[r] * CD + k] - g_zf[(size_t)(row0 + r) * CD + k];
        s += d * d;
    }
    red[threadIdx.x] = s;
    __syncthreads();
    for (int off = 128; off > 0; off >>= 1) {
        if (threadIdx.x < off) red[threadIdx.x] += red[threadIdx.x + off];
        __syncthreads();
    }
    if (threadIdx.x == 0) g_lpart[blockIdx.x] = red[0];
}

__global__ void k_final(float* out_loss) {
    __shared__ float red[256];
    float s = (threadIdx.x < M_TOK / 64) ? g_lpart[threadIdx.x] : 0.f;
    red[threadIdx.x] = s;
    __syncthreads();
    for (int off = 128; off > 0; off >>= 1) {
        if (threadIdx.x < off) red[threadIdx.x] += red[threadIdx.x + off];
        __syncthreads();
    }
    if (threadIdx.x == 0) out_loss[0] = 3.0f * red[0] / (float)((size_t)M_TOK * CD);
}

extern "C" void kernel_launch(void* const* d_in, const int* in_sizes, int n_in,
                              void* d_out, int out_size) {
    const float* z   = (const float*)d_in[0];
    const float* emb = (const float*)d_in[1];
    const float* Wc  = (const float*)d_in[2];
    const float* bc  = (const float*)d_in[3];
    const float* We  = (const float*)d_in[4];
    const float* be  = (const float*)d_in[5];
    float* out = (float*)d_out;

    cudaFuncSetAttribute(k_dist, cudaFuncAttributeMaxDynamicSharedMemorySize, SMEM_DIST);
    cudaFuncSetAttribute(k_expand, cudaFuncAttributeMaxDynamicSharedMemorySize, SMEM_EXP);

    k_prepE<<<NE, 256>>>(emb);
    k_splitWt<<<dim3(8, 24), dim3(32, 8)>>>(We);
    k_compress<<<M_TOK / 64, 256>>>(z, Wc, bc);
    k_dist<<<296, 256, SMEM_DIST>>>();
    k_pick<<<(M_TOK + 255) / 256, 256>>>();
    k_expand<<<NUEXP, 512, SMEM_EXP>>>(be, out);
    k_loss<<<M_TOK / 64, 256>>>(emb);
    if (out_size > M_TOK * CIN) k_final<<<1, 256>>>(out + (size_t)M_TOK * CIN);
}

// round 15
// speedup vs baseline: 4.1359x; 1.0005x over previous
#include <cuda_runtime.h>
#include <cuda_fp16.h>
#include <cstdint>

#define M_TOK 12608   // 64*197
#define M_PAD 12672   // 99*128
#define CIN   768
#define CD    256
#define NE    8192
#define NS    64      // code tiles (8192/128) -> partial argmin slots
#define NUNIT (99*64) // token tiles * code tiles
#define NUEXP (99*3)  // token tiles * n tiles (768/256)

// ---- device scratch (allocation-free per harness rules) ----
__device__ float g_zf[M_TOK * CD];
__device__ float g_enorm[NE];
__device__ __half g_Ah[(size_t)M_PAD * 512];  // [zh(256) | zm(256)] per token (pad rows stay 0)
__device__ __half g_Eh[(size_t)NE * 512];     // [eh(256) | em(256)] per code
__device__ __half g_Wt[(size_t)CIN * 512];    // transposed We splits: [wh(256) | wm(256)] per n-row
__device__ float g_cval[NS * M_TOK];
__device__ int   g_cidx[NS * M_TOK];
__device__ int   g_idx[M_TOK];
__device__ float g_lpart[M_TOK / 64];

// ======================= PTX helpers ========================================
__device__ __forceinline__ uint32_t smem_u32(const void* p) {
    uint32_t a;
    asm("{ .reg .u64 t; cvta.to.shared.u64 t, %1; cvt.u32.u64 %0, t; }" : "=r"(a) : "l"(p));
    return a;
}
#define CPASYNC16(dst, src) asm volatile("cp.async.cg.shared.global [%0], [%1], 16;" :: "r"(dst), "l"(src) : "memory")
#define CPCOMMIT() asm volatile("cp.async.commit_group;" ::: "memory")
#define CPWAIT1()  asm volatile("cp.async.wait_group 1;" ::: "memory")
#define CPWAIT0()  asm volatile("cp.async.wait_group 0;" ::: "memory")

__device__ __forceinline__ void ldsm_x4(uint32_t& r0, uint32_t& r1, uint32_t& r2,
                                        uint32_t& r3, uint32_t addr) {
    asm volatile("ldmatrix.sync.aligned.m8n8.x4.shared.b16 {%0,%1,%2,%3}, [%4];"
                 : "=r"(r0), "=r"(r1), "=r"(r2), "=r"(r3) : "r"(addr));
}
__device__ __forceinline__ void mma16816(float* c, const uint32_t* a, const uint32_t* b) {
    asm volatile(
        "mma.sync.aligned.m16n8k16.row.col.f32.f16.f16.f32 "
        "{%0,%1,%2,%3}, {%4,%5,%6,%7}, {%8,%9}, {%0,%1,%2,%3};"
        : "+f"(c[0]), "+f"(c[1]), "+f"(c[2]), "+f"(c[3])
        : "r"(a[0]), "r"(a[1]), "r"(a[2]), "r"(a[3]), "r"(b[0]), "r"(b[1]));
}

// ===================== prep E: ||e||^2 + fp16 2-way split ===================
__global__ void k_prepE(const float* __restrict__ E) {
    __shared__ float red[8];
    int row = blockIdx.x, c = threadIdx.x;
    float v = E[(size_t)row * CD + c];
    __half h = __float2half_rn(v);
    float r = v - __half2float(h);
    __half m = __float2half_rn(r);
    size_t b = (size_t)row * 512;
    g_Eh[b + c] = h; g_Eh[b + 256 + c] = m;
    float s = v * v;
#pragma unroll
    for (int off = 16; off > 0; off >>= 1) s += __shfl_down_sync(0xffffffffu, s, off);
    if ((c & 31) == 0) red[c >> 5] = s;
    __syncthreads();
    if (c == 0) {
        float t = 0.f;
#pragma unroll
        for (int w = 0; w < 8; w++) t += red[w];
        g_enorm[row] = t;
    }
}

// ===================== transpose + split We -> g_Wt ========================
__global__ void k_splitWt(const float* __restrict__ We) {
    __shared__ float t[32][33];
    int k0 = blockIdx.x * 32, n0 = blockIdx.y * 32;
    int tx = threadIdx.x, ty = threadIdx.y;  // 32 x 8
#pragma unroll
    for (int r = 0; r < 32; r += 8)
        t[ty + r][tx] = We[(size_t)(k0 + ty + r) * CIN + n0 + tx];
    __syncthreads();
#pragma unroll
    for (int r = 0; r < 32; r += 8) {
        int n = n0 + ty + r, k = k0 + tx;
        float v = t[tx][ty + r];
        __half h = __float2half_rn(v);
        __half m = __float2half_rn(v - __half2float(h));
        g_Wt[(size_t)n * 512 + k] = h;
        g_Wt[(size_t)n * 512 + 256 + k] = m;
    }
}

// ===================== compress GEMM + fused zf split =======================
__global__ __launch_bounds__(256, 2) void k_compress(const float* __restrict__ Z,
                                                     const float* __restrict__ W,
                                                     const float* __restrict__ bias) {
    __shared__ float As[2][8][64];
    __shared__ float Bs[2][8][256];
    int tid = threadIdx.x, tx = tid & 31, ty = tid >> 5;
    int row0 = blockIdx.x * 64;
    int aTok = tid >> 1, aK = (tid & 1) * 4;
    int bK0 = tid >> 6, bC0 = (tid & 63) * 4;
    int bK1 = (tid + 256) >> 6, bC1 = ((tid + 256) & 63) * 4;

    float acc[8][8] = {};
    float4 aReg = {}, bReg0, bReg1;

    if (tid < 128) aReg = *(const float4*)&Z[(size_t)(row0 + aTok) * CIN + aK];
    bReg0 = *(const float4*)&W[(size_t)bK0 * CD + bC0];
    bReg1 = *(const float4*)&W[(size_t)bK1 * CD + bC1];
    if (tid < 128) {
        As[0][aK + 0][aTok] = aReg.x; As[0][aK + 1][aTok] = aReg.y;
        As[0][aK + 2][aTok] = aReg.z; As[0][aK + 3][aTok] = aReg.w;
    }
    *(float4*)&Bs[0][bK0][bC0] = bReg0;
    *(float4*)&Bs[0][bK1][bC1] = bReg1;
    __syncthreads();

    const int KT = CIN / 8;
    for (int kt = 0; kt < KT; kt++) {
        int cur = kt & 1, nxt = cur ^ 1;
        if (kt + 1 < KT) {
            int kk = (kt + 1) * 8;
            if (tid < 128) aReg = *(const float4*)&Z[(size_t)(row0 + aTok) * CIN + kk + aK];
            bReg0 = *(const float4*)&W[(size_t)(kk + bK0) * CD + bC0];
            bReg1 = *(const float4*)&W[(size_t)(kk + bK1) * CD + bC1];
        }
#pragma unroll
        for (int k = 0; k < 8; k++) {
            float4 a0 = *(float4*)&As[cur][k][ty * 4];
            float4 a1 = *(float4*)&As[cur][k][32 + ty * 4];
            float4 b0 = *(float4*)&Bs[cur][k][tx * 4];
            float4 b1 = *(float4*)&Bs[cur][k][128 + tx * 4];
            float ar[8] = {a0.x, a0.y, a0.z, a0.w, a1.x, a1.y, a1.z, a1.w};
            float br[8] = {b0.x, b0.y, b0.z, b0.w, b1.x, b1.y, b1.z, b1.w};
#pragma unroll
            for (int i = 0; i < 8; i++)
#pragma unroll
                for (int j = 0; j < 8; j++) acc[i][j] = fmaf(ar[i], br[j], acc[i][j]);
        }
        if (kt + 1 < KT) {
            if (tid < 128) {
                As[nxt][aK + 0][aTok] = aReg.x; As[nxt][aK + 1][aTok] = aReg.y;
                As[nxt][aK + 2][aTok] = aReg.z; As[nxt][aK + 3][aTok] = aReg.w;
            }
            *(float4*)&Bs[nxt][bK0][bC0] = bReg0;
            *(float4*)&Bs[nxt][bK1][bC1] = bReg1;
        }
        __syncthreads();
    }

    float4 bb0 = *(const float4*)&bias[tx * 4];
    float4 bb1 = *(const float4*)&bias[128 + tx * 4];
#pragma unroll
    for (int i = 0; i < 8; i++) {
        int row = row0 + ((i < 4) ? ty * 4 + i : 32 + ty * 4 + (i - 4));
        float o[8] = {acc[i][0] + bb0.x, acc[i][1] + bb0.y, acc[i][2] + bb0.z, acc[i][3] + bb0.w,
                      acc[i][4] + bb1.x, acc[i][5] + bb1.y, acc[i][6] + bb1.z, acc[i][7] + bb1.w};
        *(float4*)&g_zf[(size_t)row * CD + tx * 4] = *(float4*)&o[0];
        *(float4*)&g_zf[(size_t)row * CD + 128 + tx * 4] = *(float4*)&o[4];
        size_t zb = (size_t)row * 512;
#pragma unroll
        for (int half_ = 0; half_ < 2; half_++) {
            int cbase = half_ * 128 + tx * 4;
            __half h[4], m[4];
#pragma unroll
            for (int j = 0; j < 4; j++) {
                float v = o[half_ * 4 + j];
                h[j] = __float2half_rn(v);
                m[j] = __float2half_rn(v - __half2float(h[j]));
            }
            *(__half2*)&g_Ah[zb + cbase]       = __halves2half2(h[0], h[1]);
            *(__half2*)&g_Ah[zb + cbase + 2]   = __halves2half2(h[2], h[3]);
            *(__half2*)&g_Ah[zb + 256 + cbase]     = __halves2half2(m[0], m[1]);
            *(__half2*)&g_Ah[zb + 256 + cbase + 2] = __halves2half2(m[2], m[3]);
        }
    }
}

// ===================== HMMA distance + argmin ===============================
// Persistent grid=296 (2 CTAs/SM), 256 threads (8 warps, 4m x 2n).
// Unit = 128 tokens x 128 codes. K = 3 segs x 256 = 12 chunks of 64:
// A {zh,zm,zh}, B {eh,eh,em}. 3-stage ring + cross-unit prefetch.
#define DS_STAGE 32768
#define DSA(st) ((st) * DS_STAGE)
#define DSB(st) ((st) * DS_STAGE + 16384)
#define DS_SVAL 98304
#define DS_SIDX 99328
#define SMEM_DIST 100352

__device__ __forceinline__ void dist_load(uint32_t sb, int tid,
                                          const __half* Abase, const __half* Bbase,
                                          int c, int st, bool valid) {
    if (valid) {
        int seg = c >> 2, w = c & 3;
        int aoff = ((seg == 1) ? 256 : 0) + w * 64;  // zh, zm, zh
        int boff = ((seg == 2) ? 256 : 0) + w * 64;  // eh, eh, em
#pragma unroll
        for (int t = 0; t < 4; t++) {  // A: 128 rows x 128B
            int uu = tid + t * 256;
            int row = uu >> 3, q8 = uu & 7;
            const void* src = Abase + (size_t)row * 512 + aoff + q8 * 8;
            int bo = row * 128 + q8 * 16;
            CPASYNC16(sb + DSA(st) + (uint32_t)(bo ^ ((row & 7) << 4)), src);
        }
#pragma unroll
        for (int t = 0; t < 4; t++) {  // B: 128 rows x 128B
            int uu = tid + t * 256;
            int row = uu >> 3, q8 = uu & 7;
            const void* src = Bbase + (size_t)row * 512 + boff + q8 * 8;
            int bo = row * 128 + q8 * 16;
            CPASYNC16(sb + DSB(st) + (uint32_t)(bo ^ ((row & 7) << 4)), src);
        }
    }
    CPCOMMIT();
}

__global__ __launch_bounds__(256, 2) void k_dist() {
    extern __shared__ char sm[];
    uint32_t sb = smem_u32(sm);
    float* sval = (float*)(sm + DS_SVAL);
    int*   sidx = (int*)(sm + DS_SIDX);
    int tid = threadIdx.x, lane = tid & 31, wid = tid >> 5;
    int wm = wid >> 1, wn = wid & 1;
    int q = lane >> 3, rw = lane & 7;

    uint32_t aRow = (uint32_t)((wm * 32 + ((q & 1) << 3) + rw) * 128);
    uint32_t aKq = (uint32_t)((q >> 1) << 4);
    uint32_t bRow = (uint32_t)((wn * 64 + ((q >> 1) << 3) + rw) * 128);
    uint32_t bKq = (uint32_t)((q & 1) << 4);
    uint32_t swz = (uint32_t)(rw << 4);

    int u = blockIdx.x;
    const __half* Ab = &g_Ah[(size_t)(u >> 6) * 128 * 512];
    const __half* Bb = &g_Eh[(size_t)(u & 63) * 128 * 512];
    int st = 0;
    dist_load(sb, tid, Ab, Bb, 0, 0, u < NUNIT);
    dist_load(sb, tid, Ab, Bb, 1, 1, u < NUNIT);

    for (; u < NUNIT; u += gridDim.x) {
        int tt = u >> 6, ct = u & 63;
        int tok0 = tt * 128, c0 = ct * 128;
        int un = u + gridDim.x;
        // pointer arithmetic only when un >= NUNIT (never dereferenced)
        const __half* Abn = &g_Ah[(size_t)(un >> 6) * 128 * 512];
        const __half* Bbn = &g_Eh[(size_t)(un & 63) * 128 * 512];

        float acc[2][8][4];
#pragma unroll
        for (int mt = 0; mt < 2; mt++)
#pragma unroll
            for (int nt = 0; nt < 8; nt++)
#pragma unroll
                for (int e = 0; e < 4; e++) acc[mt][nt][e] = 0.f;

        for (int c = 0; c < 12; c++) {
            CPWAIT1();
            __syncthreads();
            int st2 = st + 2; if (st2 >= 3) st2 -= 3;
            if (c < 10) dist_load(sb, tid, Ab, Bb, c + 2, st2, true);
            else        dist_load(sb, tid, Abn, Bbn, c - 10, st2, un < NUNIT);
#pragma unroll
            for (int ks = 0; ks < 4; ks++) {
                uint32_t a[2][4];
#pragma unroll
                for (int mt = 0; mt < 2; mt++)
                    ldsm_x4(a[mt][0], a[mt][1], a[mt][2], a[mt][3],
                            sb + DSA(st) + aRow + mt * 2048 + (((uint32_t)(ks * 32) + aKq) ^ swz));
                uint32_t b[8][2];
#pragma unroll
                for (int p = 0; p < 4; p++)
                    ldsm_x4(b[2 * p][0], b[2 * p][1], b[2 * p + 1][0], b[2 * p + 1][1],
                            sb + DSB(st) + bRow + p * 2048 + (((uint32_t)(ks * 32) + bKq) ^ swz));
#pragma unroll
                for (int mt = 0; mt < 2; mt++)
#pragma unroll
                    for (int nt = 0; nt < 8; nt++)
                        mma16816(acc[mt][nt], a[mt], b[nt]);
            }
            if (++st >= 3) st = 0;
        }

        // epilogue: d = ||e||^2 - 2 z.e ; strict < keeps lowest index
        float bestv[2][2]; int besti[2][2];
#pragma unroll
        for (int mt = 0; mt < 2; mt++)
#pragma unroll
            for (int key = 0; key < 2; key++) { bestv[mt][key] = 3.4e38f; besti[mt][key] = 0; }
#pragma unroll
        for (int nt = 0; nt < 8; nt++) {
            int colb = c0 + wn * 64 + nt * 8 + 2 * (lane & 3);
            float en0 = __ldg(&g_enorm[colb]);
            float en1 = __ldg(&g_enorm[colb + 1]);
#pragma unroll
            for (int mt = 0; mt < 2; mt++) {
#pragma unroll
                for (int key = 0; key < 2; key++) {
                    float d0 = en0 - 2.0f * acc[mt][nt][key * 2 + 0];
                    if (d0 < bestv[mt][key]) { bestv[mt][key] = d0; besti[mt][key] = colb; }
                    float d1 = en1 - 2.0f * acc[mt][nt][key * 2 + 1];
                    if (d1 < bestv[mt][key]) { bestv[mt][key] = d1; besti[mt][key] = colb + 1; }
                }
            }
        }
#pragma unroll
        for (int mt = 0; mt < 2; mt++)
#pragma unroll
            for (int key = 0; key < 2; key++) {
                float v = bestv[mt][key]; int bi = besti[mt][key];
#pragma unroll
                for (int off = 1; off <= 2; off <<= 1) {
                    float ov = __shfl_xor_sync(0xffffffffu, v, off);
                    int   oi = __shfl_xor_sync(0xffffffffu, bi, off);
                    if (ov < v || (ov == v && oi < bi)) { v = ov; bi = oi; }
                }
                if ((lane & 3) == 0) {
                    int rowL = wm * 32 + mt * 16 + key * 8 + (lane >> 2);
                    sval[wn * 128 + rowL] = v;
                    sidx[wn * 128 + rowL] = bi;
                }
            }
        __syncthreads();
        if (tid < 128) {
            float v = sval[tid]; int bi = sidx[tid];
            float ov = sval[128 + tid]; int oi = sidx[128 + tid];
            if (ov < v || (ov == v && oi < bi)) { v = ov; bi = oi; }
            int tok = tok0 + tid;
            if (tok < M_TOK) {
                g_cval[ct * M_TOK + tok] = v;
                g_cidx[ct * M_TOK + tok] = bi;
            }
        }
        __syncthreads();
        Ab = Abn; Bb = Bbn;
    }
}

// ===================== reduce over code-tile partials ========================
__global__ void k_pick() {
    int m = blockIdx.x * blockDim.x + threadIdx.x;
    if (m >= M_TOK) return;
    float bv = g_cval[m]; int bi = g_cidx[m];
#pragma unroll 8
    for (int s = 1; s < NS; s++) {
        float v = g_cval[s * M_TOK + m]; int ii = g_cidx[s * M_TOK + m];
        if (v < bv || (v == bv && ii < bi)) { bv = v; bi = ii; }
    }
    g_idx[m] = bi;
}

// ===================== HMMA expand: out = emb[idx] @ We + be ================
#define ES_STAGE 49152
#define ESA(st) ((st) * ES_STAGE)
#define ESB(st) ((st) * ES_STAGE + 16384)
#define EX_IDX 147456
#define SMEM_EXP 147968

__global__ __launch_bounds__(512, 1) void k_expand(const float* __restrict__ bias,
                                                   float* __restrict__ out) {
    extern __shared__ char sm[];
    uint32_t sb = smem_u32(sm);
    int* idxS = (int*)(sm + EX_IDX);
    int tid = threadIdx.x, lane = tid & 31, wid = tid >> 5;
    int wm = wid >> 2, wn = wid & 3;
    int q = lane >> 3, rw = lane & 7;

    uint32_t aRow = (uint32_t)((wm * 32 + ((q & 1) << 3) + rw) * 128);
    uint32_t aKq = (uint32_t)((q >> 1) << 4);
    uint32_t bRow = (uint32_t)((wn * 64 + ((q >> 1) << 3) + rw) * 128);
    uint32_t bKq = (uint32_t)((q & 1) << 4);
    uint32_t swz = (uint32_t)(rw << 4);

    int u = blockIdx.x;
    int tt = u / 3, n3 = u - tt * 3;
    int tok0 = tt * 128, ncol0 = n3 * 256;

    if (tid < 128) {
        int tok = tok0 + tid;
        idxS[tid] = (tok < M_TOK) ? g_idx[tok] : 0;
    }
    __syncthreads();

    const __half* Bbase = &g_Wt[(size_t)ncol0 * 512];

    float acc[2][8][4];
#pragma unroll
    for (int mt = 0; mt < 2; mt++)
#pragma unroll
        for (int nt = 0; nt < 8; nt++)
#pragma unroll
            for (int e = 0; e < 4; e++) acc[mt][nt][e] = 0.f;

    auto load = [&](int c, int st) {
        int seg = c >> 2, w = c & 3;
        int aoff = ((seg == 1) ? 256 : 0) + w * 64;  // eh, em, eh
        int boff = ((seg == 2) ? 256 : 0) + w * 64;  // wh, wh, wm
#pragma unroll
        for (int t = 0; t < 2; t++) {
            int uu = tid + t * 512;
            int row = uu >> 3, q8 = uu & 7;
            const void* src = &g_Eh[(size_t)idxS[row] * 512 + aoff + q8 * 8];
            int bo = row * 128 + q8 * 16;
            CPASYNC16(sb + ESA(st) + (uint32_t)(bo ^ ((row & 7) << 4)), src);
        }
#pragma unroll
        for (int t = 0; t < 4; t++) {
            int uu = tid + t * 512;
            int row = uu >> 3, q8 = uu & 7;
            const void* src = Bbase + (size_t)row * 512 + boff + q8 * 8;
            int bo = row * 128 + q8 * 16;
            CPASYNC16(sb + ESB(st) + (uint32_t)(bo ^ ((row & 7) << 4)), src);
        }
        CPCOMMIT();
    };

    load(0, 0);
    load(1, 1);
    int st = 0;
    for (int c = 0; c < 12; c++) {
        if (c < 11) CPWAIT1(); else CPWAIT0();
        __syncthreads();
        if (c + 2 < 12) {
            int st2 = st + 2; if (st2 >= 3) st2 -= 3;
            load(c + 2, st2);
        }
#pragma unroll
        for (int ks = 0; ks < 4; ks++) {
            uint32_t a[2][4];
#pragma unroll
            for (int mt = 0; mt < 2; mt++)
                ldsm_x4(a[mt][0], a[mt][1], a[mt][2], a[mt][3],
                        sb + ESA(st) + aRow + mt * 2048 + (((uint32_t)(ks * 32) + aKq) ^ swz));
            uint32_t b[8][2];
#pragma unroll
            for (int p = 0; p < 4; p++)
                ldsm_x4(b[2 * p][0], b[2 * p][1], b[2 * p + 1][0], b[2 * p + 1][1],
                        sb + ESB(st) + bRow + p * 2048 + (((uint32_t)(ks * 32) + bKq) ^ swz));
#pragma unroll
            for (int mt = 0; mt < 2; mt++)
#pragma unroll
                for (int nt = 0; nt < 8; nt++)
                    mma16816(acc[mt][nt], a[mt], b[nt]);
        }
        if (++st >= 3) st = 0;
    }

#pragma unroll
    for (int nt = 0; nt < 8; nt++) {
        int col = ncol0 + wn * 64 + nt * 8 + 2 * (lane & 3);
        float b0 = __ldg(&bias[col]), b1 = __ldg(&bias[col + 1]);
#pragma unroll
        for (int mt = 0; mt < 2; mt++) {
#pragma unroll
            for (int key = 0; key < 2; key++) {
                int tok = tok0 + wm * 32 + mt * 16 + key * 8 + (lane >> 2);
                if (tok < M_TOK) {
                    float2 o = {acc[mt][nt][key * 2 + 0] + b0, acc[mt][nt][key * 2 + 1] + b1};
                    *(float2*)&out[(size_t)tok * CIN + col] = o;
                }
            }
        }
    }
}

// ===================== loss partials =====================
__global__ void k_loss(const float* __restrict__ E) {
    __shared__ int idxS[64];
    __shared__ float red[256];
    int row0 = blockIdx.x * 64;
    if (threadIdx.x < 64) idxS[threadIdx.x] = g_idx[row0 + threadIdx.x];
    __syncthreads();
    float s = 0.f;
    for (int idx = threadIdx.x; idx < 64 * CD; idx += 256) {
        int r = idx >> 8, k = idx & 255;
        float d = E[(size_t)idxS[r] * CD + k] - g_zf[(size_t)(row0 + r) * CD + k];
        s += d * d;
    }
    red[threadIdx.x] = s;
    __syncthreads();
    for (int off = 128; off > 0; off >>= 1) {
        if (threadIdx.x < off) red[threadIdx.x] += red[threadIdx.x + off];
        __syncthreads();
    }
    if (threadIdx.x == 0) g_lpart[blockIdx.x] = red[0];
}

__global__ void k_final(float* out_loss) {
    __shared__ float red[256];
    float s = (threadIdx.x < M_TOK / 64) ? g_lpart[threadIdx.x] : 0.f;
    red[threadIdx.x] = s;
    __syncthreads();
    for (int off = 128; off > 0; off >>= 1) {
        if (threadIdx.x < off) red[threadIdx.x] += red[threadIdx.x + off];
        __syncthreads();
    }
    if (threadIdx.x == 0) out_loss[0] = 3.0f * red[0] / (float)((size_t)M_TOK * CD);
}

extern "C" void kernel_launch(void* const* d_in, const int* in_sizes, int n_in,
                              void* d_out, int out_size) {
    const float* z   = (const float*)d_in[0];
    const float* emb = (const float*)d_in[1];
    const float* Wc  = (const float*)d_in[2];
    const float* bc  = (const float*)d_in[3];
    const float* We  = (const float*)d_in[4];
    const float* be  = (const float*)d_in[5];
    float* out = (float*)d_out;

    cudaFuncSetAttribute(k_dist, cudaFuncAttributeMaxDynamicSharedMemorySize, SMEM_DIST);
    cudaFuncSetAttribute(k_expand, cudaFuncAttributeMaxDynamicSharedMemorySize, SMEM_EXP);

    k_prepE<<<NE, 256>>>(emb);
    k_splitWt<<<dim3(8, 24), dim3(32, 8)>>>(We);
    k_compress<<<M_TOK / 64, 256>>>(z, Wc, bc);
    k_dist<<<296, 256, SMEM_DIST>>>();
    k_pick<<<(M_TOK + 255) / 256, 256>>>();
    k_expand<<<NUEXP, 512, SMEM_EXP>>>(be, out);
    k_loss<<<M_TOK / 64, 256>>>(emb);
    if (out_size > M_TOK * CIN) k_final<<<1, 256>>>(out + (size_t)M_TOK * CIN);
}

// round 16
// speedup vs baseline: 4.8197x; 1.1653x over previous
#include <cuda_runtime.h>
#include <cuda_fp16.h>
#include <cstdint>

#define M_TOK 12608   // 64*197
#define M_PAD 12672   // 99*128
#define CIN   768
#define CD    256
#define NE    8192
#define NS    64      // code tiles (8192/128) -> partial argmin slots
#define NUNIT (99*64) // token tiles * code tiles
#define NUEXP (99*3)  // token tiles * n tiles (768/256)

// ---- device scratch (allocation-free per harness rules) ----
__device__ float g_zf[M_TOK * CD];
__device__ float g_enorm[NE];
__device__ __half g_Ah[(size_t)M_PAD * 512];   // [zh(256) | zm(256)] per token (pad rows stay 0)
__device__ __half g_Eh[(size_t)NE * 512];      // [eh(256) | em(256)] per code
__device__ __half g_Wt[(size_t)CIN * 512];     // transposed We splits per n-row
__device__ __half g_Zs[(size_t)M_PAD * 1536];  // input z splits: [zh(768) | zm(768)]
__device__ __half g_Wcs[(size_t)CD * 1536];    // transposed Wc splits per n-row
__device__ float g_cval[NS * M_TOK];
__device__ int   g_cidx[NS * M_TOK];
__device__ int   g_idx[M_TOK];
__device__ float g_lpart[M_TOK / 64];

// ======================= PTX helpers ========================================
__device__ __forceinline__ uint32_t smem_u32(const void* p) {
    uint32_t a;
    asm("{ .reg .u64 t; cvta.to.shared.u64 t, %1; cvt.u32.u64 %0, t; }" : "=r"(a) : "l"(p));
    return a;
}
#define CPASYNC16(dst, src) asm volatile("cp.async.cg.shared.global [%0], [%1], 16;" :: "r"(dst), "l"(src) : "memory")
#define CPCOMMIT() asm volatile("cp.async.commit_group;" ::: "memory")
#define CPWAIT1()  asm volatile("cp.async.wait_group 1;" ::: "memory")
#define CPWAIT0()  asm volatile("cp.async.wait_group 0;" ::: "memory")

__device__ __forceinline__ void ldsm_x4(uint32_t& r0, uint32_t& r1, uint32_t& r2,
                                        uint32_t& r3, uint32_t addr) {
    asm volatile("ldmatrix.sync.aligned.m8n8.x4.shared.b16 {%0,%1,%2,%3}, [%4];"
                 : "=r"(r0), "=r"(r1), "=r"(r2), "=r"(r3) : "r"(addr));
}
__device__ __forceinline__ void mma16816(float* c, const uint32_t* a, const uint32_t* b) {
    asm volatile(
        "mma.sync.aligned.m16n8k16.row.col.f32.f16.f16.f32 "
        "{%0,%1,%2,%3}, {%4,%5,%6,%7}, {%8,%9}, {%0,%1,%2,%3};"
        : "+f"(c[0]), "+f"(c[1]), "+f"(c[2]), "+f"(c[3])
        : "r"(a[0]), "r"(a[1]), "r"(a[2]), "r"(a[3]), "r"(b[0]), "r"(b[1]));
}

// ===================== prep E: ||e||^2 + fp16 2-way split ===================
__global__ void k_prepE(const float* __restrict__ E) {
    __shared__ float red[8];
    int row = blockIdx.x, c = threadIdx.x;
    float v = E[(size_t)row * CD + c];
    __half h = __float2half_rn(v);
    float r = v - __half2float(h);
    __half m = __float2half_rn(r);
    size_t b = (size_t)row * 512;
    g_Eh[b + c] = h; g_Eh[b + 256 + c] = m;
    float s = v * v;
#pragma unroll
    for (int off = 16; off > 0; off >>= 1) s += __shfl_down_sync(0xffffffffu, s, off);
    if ((c & 31) == 0) red[c >> 5] = s;
    __syncthreads();
    if (c == 0) {
        float t = 0.f;
#pragma unroll
        for (int w = 0; w < 8; w++) t += red[w];
        g_enorm[row] = t;
    }
}

// ===================== transpose + split We -> g_Wt ========================
__global__ void k_splitWt(const float* __restrict__ We) {
    __shared__ float t[32][33];
    int k0 = blockIdx.x * 32, n0 = blockIdx.y * 32;
    int tx = threadIdx.x, ty = threadIdx.y;  // 32 x 8
#pragma unroll
    for (int r = 0; r < 32; r += 8)
        t[ty + r][tx] = We[(size_t)(k0 + ty + r) * CIN + n0 + tx];
    __syncthreads();
#pragma unroll
    for (int r = 0; r < 32; r += 8) {
        int n = n0 + ty + r, k = k0 + tx;
        float v = t[tx][ty + r];
        __half h = __float2half_rn(v);
        __half m = __float2half_rn(v - __half2float(h));
        g_Wt[(size_t)n * 512 + k] = h;
        g_Wt[(size_t)n * 512 + 256 + k] = m;
    }
}

// ===================== transpose + split Wc -> g_Wcs =======================
// Wc is [CIN=768 k][CD=256 n]; g_Wcs[n][0:768]=wh(k), [768:1536]=wm(k)
__global__ void k_splitWc(const float* __restrict__ Wc) {
    __shared__ float t[32][33];
    int k0 = blockIdx.x * 32, n0 = blockIdx.y * 32;
    int tx = threadIdx.x, ty = threadIdx.y;  // 32 x 8
#pragma unroll
    for (int r = 0; r < 32; r += 8)
        t[ty + r][tx] = Wc[(size_t)(k0 + ty + r) * CD + n0 + tx];
    __syncthreads();
#pragma unroll
    for (int r = 0; r < 32; r += 8) {
        int n = n0 + ty + r, k = k0 + tx;
        float v = t[tx][ty + r];
        __half h = __float2half_rn(v);
        __half m = __float2half_rn(v - __half2float(h));
        g_Wcs[(size_t)n * 1536 + k] = h;
        g_Wcs[(size_t)n * 1536 + 768 + k] = m;
    }
}

// ===================== split input z -> g_Zs ================================
__global__ void k_splitZin(const float* __restrict__ Z) {
    int row = blockIdx.x, c = threadIdx.x;
    size_t b = (size_t)row * 1536;
#pragma unroll
    for (int j = 0; j < 3; j++) {
        int cc = j * 256 + c;
        float v = (row < M_TOK) ? Z[(size_t)row * CIN + cc] : 0.f;
        __half h = __float2half_rn(v);
        __half m = __float2half_rn(v - __half2float(h));
        g_Zs[b + cc] = h;
        g_Zs[b + 768 + cc] = m;
    }
}

// ===================== HMMA compress: zf = z @ Wc + bc =====================
// 99 CTAs x 512 threads (warp grid 4m x 4n, warp 32 tok x 64 cols).
// Unit = 128 tok x 256 cols. K = 3 segs x 768 = 36 chunks of 64:
// A {zh, zm, zh}, B {wh, wh, wm}. Epilogue writes g_zf + g_Ah split.
#define CS_STAGE 49152
#define CSA(st) ((st) * CS_STAGE)
#define CSB(st) ((st) * CS_STAGE + 16384)
#define SMEM_CMP 147456

__global__ __launch_bounds__(512, 1) void k_compressH(const float* __restrict__ bias) {
    extern __shared__ char sm[];
    uint32_t sb = smem_u32(sm);
    int tid = threadIdx.x, lane = tid & 31, wid = tid >> 5;
    int wm = wid >> 2, wn = wid & 3;
    int q = lane >> 3, rw = lane & 7;

    uint32_t aRow = (uint32_t)((wm * 32 + ((q & 1) << 3) + rw) * 128);
    uint32_t aKq = (uint32_t)((q >> 1) << 4);
    uint32_t bRow = (uint32_t)((wn * 64 + ((q >> 1) << 3) + rw) * 128);
    uint32_t bKq = (uint32_t)((q & 1) << 4);
    uint32_t swz = (uint32_t)(rw << 4);

    int tok0 = blockIdx.x * 128;

    float acc[2][8][4];
#pragma unroll
    for (int mt = 0; mt < 2; mt++)
#pragma unroll
        for (int nt = 0; nt < 8; nt++)
#pragma unroll
            for (int e = 0; e < 4; e++) acc[mt][nt][e] = 0.f;

    auto load = [&](int c, int st) {
        int seg = c / 12, w = c % 12;
        int aoff = ((seg == 1) ? 768 : 0) + w * 64;  // zh, zm, zh
        int boff = ((seg == 2) ? 768 : 0) + w * 64;  // wh, wh, wm
#pragma unroll
        for (int t = 0; t < 2; t++) {  // A: 128 rows x 128B
            int uu = tid + t * 512;
            int row = uu >> 3, q8 = uu & 7;
            const void* src = &g_Zs[(size_t)(tok0 + row) * 1536 + aoff + q8 * 8];
            int bo = row * 128 + q8 * 16;
            CPASYNC16(sb + CSA(st) + (uint32_t)(bo ^ ((row & 7) << 4)), src);
        }
#pragma unroll
        for (int t = 0; t < 4; t++) {  // B: 256 rows x 128B
            int uu = tid + t * 512;
            int row = uu >> 3, q8 = uu & 7;
            const void* src = &g_Wcs[(size_t)row * 1536 + boff + q8 * 8];
            int bo = row * 128 + q8 * 16;
            CPASYNC16(sb + CSB(st) + (uint32_t)(bo ^ ((row & 7) << 4)), src);
        }
        CPCOMMIT();
    };

    load(0, 0);
    load(1, 1);
    for (int cc = 0; cc < 12; cc++) {
#pragma unroll
        for (int s3 = 0; s3 < 3; s3++) {
            int c = cc * 3 + s3;
            if (c < 35) CPWAIT1(); else CPWAIT0();
            __syncthreads();
            if (c + 2 < 36) load(c + 2, (s3 + 2) % 3);
#pragma unroll
            for (int ks = 0; ks < 4; ks++) {
                uint32_t a[2][4];
#pragma unroll
                for (int mt = 0; mt < 2; mt++)
                    ldsm_x4(a[mt][0], a[mt][1], a[mt][2], a[mt][3],
                            sb + CSA(s3) + aRow + mt * 2048 + (((uint32_t)(ks * 32) + aKq) ^ swz));
                uint32_t b[8][2];
#pragma unroll
                for (int p = 0; p < 4; p++)
                    ldsm_x4(b[2 * p][0], b[2 * p][1], b[2 * p + 1][0], b[2 * p + 1][1],
                            sb + CSB(s3) + bRow + p * 2048 + (((uint32_t)(ks * 32) + bKq) ^ swz));
#pragma unroll
                for (int mt = 0; mt < 2; mt++)
#pragma unroll
                    for (int nt = 0; nt < 8; nt++)
                        mma16816(acc[mt][nt], a[mt], b[nt]);
            }
        }
    }

    // epilogue: zf = acc + bc ; also write fp16 2-way split into g_Ah
#pragma unroll
    for (int nt = 0; nt < 8; nt++) {
        int col = wn * 64 + nt * 8 + 2 * (lane & 3);
        float b0 = __ldg(&bias[col]), b1 = __ldg(&bias[col + 1]);
#pragma unroll
        for (int mt = 0; mt < 2; mt++) {
#pragma unroll
            for (int key = 0; key < 2; key++) {
                int tok = tok0 + wm * 32 + mt * 16 + key * 8 + (lane >> 2);
                if (tok < M_TOK) {
                    float v0 = acc[mt][nt][key * 2 + 0] + b0;
                    float v1 = acc[mt][nt][key * 2 + 1] + b1;
                    float2 o = {v0, v1};
                    *(float2*)&g_zf[(size_t)tok * CD + col] = o;
                    __half h0 = __float2half_rn(v0), h1 = __float2half_rn(v1);
                    __half m0 = __float2half_rn(v0 - __half2float(h0));
                    __half m1 = __float2half_rn(v1 - __half2float(h1));
                    *(__half2*)&g_Ah[(size_t)tok * 512 + col] = __halves2half2(h0, h1);
                    *(__half2*)&g_Ah[(size_t)tok * 512 + 256 + col] = __halves2half2(m0, m1);
                }
            }
        }
    }
}

// ===================== HMMA distance + argmin ===============================
// Persistent grid=296 (2 CTAs/SM), 256 threads (8 warps, 4m x 2n).
// Unit = 128 tokens x 128 codes. K = 3 segs x 256 = 12 chunks of 64:
// A {zh,zm,zh}, B {eh,eh,em}. 3-stage ring + cross-unit prefetch.
// Chunk loop is a 4x3 nest so ring-stage addresses are compile-time.
#define DS_STAGE 32768
#define DSA(st) ((st) * DS_STAGE)
#define DSB(st) ((st) * DS_STAGE + 16384)
#define DS_SVAL 98304
#define DS_SIDX 99328
#define SMEM_DIST 100352

__device__ __forceinline__ void dist_load(uint32_t sb, int tid,
                                          const __half* Abase, const __half* Bbase,
                                          int c, int st, bool valid) {
    if (valid) {
        int seg = c >> 2, w = c & 3;
        int aoff = ((seg == 1) ? 256 : 0) + w * 64;  // zh, zm, zh
        int boff = ((seg == 2) ? 256 : 0) + w * 64;  // eh, eh, em
#pragma unroll
        for (int t = 0; t < 4; t++) {  // A: 128 rows x 128B
            int uu = tid + t * 256;
            int row = uu >> 3, q8 = uu & 7;
            const void* src = Abase + (size_t)row * 512 + aoff + q8 * 8;
            int bo = row * 128 + q8 * 16;
            CPASYNC16(sb + DSA(st) + (uint32_t)(bo ^ ((row & 7) << 4)), src);
        }
#pragma unroll
        for (int t = 0; t < 4; t++) {  // B: 128 rows x 128B
            int uu = tid + t * 256;
            int row = uu >> 3, q8 = uu & 7;
            const void* src = Bbase + (size_t)row * 512 + boff + q8 * 8;
            int bo = row * 128 + q8 * 16;
            CPASYNC16(sb + DSB(st) + (uint32_t)(bo ^ ((row & 7) << 4)), src);
        }
    }
    CPCOMMIT();
}

__global__ __launch_bounds__(256, 2) void k_dist() {
    extern __shared__ char sm[];
    uint32_t sb = smem_u32(sm);
    float* sval = (float*)(sm + DS_SVAL);
    int*   sidx = (int*)(sm + DS_SIDX);
    int tid = threadIdx.x, lane = tid & 31, wid = tid >> 5;
    int wm = wid >> 1, wn = wid & 1;
    int q = lane >> 3, rw = lane & 7;

    uint32_t aRow = (uint32_t)((wm * 32 + ((q & 1) << 3) + rw) * 128);
    uint32_t aKq = (uint32_t)((q >> 1) << 4);
    uint32_t bRow = (uint32_t)((wn * 64 + ((q >> 1) << 3) + rw) * 128);
    uint32_t bKq = (uint32_t)((q & 1) << 4);
    uint32_t swz = (uint32_t)(rw << 4);

    int u = blockIdx.x;
    const __half* Ab = &g_Ah[(size_t)(u >> 6) * 128 * 512];
    const __half* Bb = &g_Eh[(size_t)(u & 63) * 128 * 512];
    dist_load(sb, tid, Ab, Bb, 0, 0, u < NUNIT);
    dist_load(sb, tid, Ab, Bb, 1, 1, u < NUNIT);

    for (; u < NUNIT; u += gridDim.x) {
        int tt = u >> 6, ct = u & 63;
        int tok0 = tt * 128, c0 = ct * 128;
        int un = u + gridDim.x;
        // pointer arithmetic only when un >= NUNIT (never dereferenced)
        const __half* Abn = &g_Ah[(size_t)(un >> 6) * 128 * 512];
        const __half* Bbn = &g_Eh[(size_t)(un & 63) * 128 * 512];

        float acc[2][8][4];
#pragma unroll
        for (int mt = 0; mt < 2; mt++)
#pragma unroll
            for (int nt = 0; nt < 8; nt++)
#pragma unroll
                for (int e = 0; e < 4; e++) acc[mt][nt][e] = 0.f;

        for (int cc = 0; cc < 4; cc++) {
#pragma unroll
            for (int s3 = 0; s3 < 3; s3++) {
                int c = cc * 3 + s3;
                CPWAIT1();
                __syncthreads();
                if (c < 10) dist_load(sb, tid, Ab, Bb, c + 2, (s3 + 2) % 3, true);
                else        dist_load(sb, tid, Abn, Bbn, c - 10, (s3 + 2) % 3, un < NUNIT);
#pragma unroll
                for (int ks = 0; ks < 4; ks++) {
                    uint32_t a[2][4];
#pragma unroll
                    for (int mt = 0; mt < 2; mt++)
                        ldsm_x4(a[mt][0], a[mt][1], a[mt][2], a[mt][3],
                                sb + DSA(s3) + aRow + mt * 2048 + (((uint32_t)(ks * 32) + aKq) ^ swz));
                    uint32_t b[8][2];
#pragma unroll
                    for (int p = 0; p < 4; p++)
                        ldsm_x4(b[2 * p][0], b[2 * p][1], b[2 * p + 1][0], b[2 * p + 1][1],
                                sb + DSB(s3) + bRow + p * 2048 + (((uint32_t)(ks * 32) + bKq) ^ swz));
#pragma unroll
                    for (int mt = 0; mt < 2; mt++)
#pragma unroll
                        for (int nt = 0; nt < 8; nt++)
                            mma16816(acc[mt][nt], a[mt], b[nt]);
                }
            }
        }

        // epilogue: d = ||e||^2 - 2 z.e ; strict < keeps lowest index
        float bestv[2][2]; int besti[2][2];
#pragma unroll
        for (int mt = 0; mt < 2; mt++)
#pragma unroll
            for (int key = 0; key < 2; key++) { bestv[mt][key] = 3.4e38f; besti[mt][key] = 0; }
#pragma unroll
        for (int nt = 0; nt < 8; nt++) {
            int colb = c0 + wn * 64 + nt * 8 + 2 * (lane & 3);
            float en0 = __ldg(&g_enorm[colb]);
            float en1 = __ldg(&g_enorm[colb + 1]);
#pragma unroll
            for (int mt = 0; mt < 2; mt++) {
#pragma unroll
                for (int key = 0; key < 2; key++) {
                    float d0 = en0 - 2.0f * acc[mt][nt][key * 2 + 0];
                    if (d0 < bestv[mt][key]) { bestv[mt][key] = d0; besti[mt][key] = colb; }
                    float d1 = en1 - 2.0f * acc[mt][nt][key * 2 + 1];
                    if (d1 < bestv[mt][key]) { bestv[mt][key] = d1; besti[mt][key] = colb + 1; }
                }
            }
        }
#pragma unroll
        for (int mt = 0; mt < 2; mt++)
#pragma unroll
            for (int key = 0; key < 2; key++) {
                float v = bestv[mt][key]; int bi = besti[mt][key];
#pragma unroll
                for (int off = 1; off <= 2; off <<= 1) {
                    float ov = __shfl_xor_sync(0xffffffffu, v, off);
                    int   oi = __shfl_xor_sync(0xffffffffu, bi, off);
                    if (ov < v || (ov == v && oi < bi)) { v = ov; bi = oi; }
                }
                if ((lane & 3) == 0) {
                    int rowL = wm * 32 + mt * 16 + key * 8 + (lane >> 2);
                    sval[wn * 128 + rowL] = v;
                    sidx[wn * 128 + rowL] = bi;
                }
            }
        __syncthreads();
        if (tid < 128) {
            float v = sval[tid]; int bi = sidx[tid];
            float ov = sval[128 + tid]; int oi = sidx[128 + tid];
            if (ov < v || (ov == v && oi < bi)) { v = ov; bi = oi; }
            int tok = tok0 + tid;
            if (tok < M_TOK) {
                g_cval[ct * M_TOK + tok] = v;
                g_cidx[ct * M_TOK + tok] = bi;
            }
        }
        __syncthreads();
        Ab = Abn; Bb = Bbn;
    }
}

// ===================== reduce over code-tile partials ========================
__global__ void k_pick() {
    int m = blockIdx.x * blockDim.x + threadIdx.x;
    if (m >= M_TOK) return;
    float bv = g_cval[m]; int bi = g_cidx[m];
#pragma unroll 8
    for (int s = 1; s < NS; s++) {
        float v = g_cval[s * M_TOK + m]; int ii = g_cidx[s * M_TOK + m];
        if (v < bv || (v == bv && ii < bi)) { bv = v; bi = ii; }
    }
    g_idx[m] = bi;
}

// ===================== HMMA expand: out = emb[idx] @ We + be ================
#define ES_STAGE 49152
#define ESA(st) ((st) * ES_STAGE)
#define ESB(st) ((st) * ES_STAGE + 16384)
#define EX_IDX 147456
#define SMEM_EXP 147968

__global__ __launch_bounds__(512, 1) void k_expand(const float* __restrict__ bias,
                                                   float* __restrict__ out) {
    extern __shared__ char sm[];
    uint32_t sb = smem_u32(sm);
    int* idxS = (int*)(sm + EX_IDX);
    int tid = threadIdx.x, lane = tid & 31, wid = tid >> 5;
    int wm = wid >> 2, wn = wid & 3;
    int q = lane >> 3, rw = lane & 7;

    uint32_t aRow = (uint32_t)((wm * 32 + ((q & 1) << 3) + rw) * 128);
    uint32_t aKq = (uint32_t)((q >> 1) << 4);
    uint32_t bRow = (uint32_t)((wn * 64 + ((q >> 1) << 3) + rw) * 128);
    uint32_t bKq = (uint32_t)((q & 1) << 4);
    uint32_t swz = (uint32_t)(rw << 4);

    int u = blockIdx.x;
    int tt = u / 3, n3 = u - tt * 3;
    int tok0 = tt * 128, ncol0 = n3 * 256;

    if (tid < 128) {
        int tok = tok0 + tid;
        idxS[tid] = (tok < M_TOK) ? g_idx[tok] : 0;
    }
    __syncthreads();

    const __half* Bbase = &g_Wt[(size_t)ncol0 * 512];

    float acc[2][8][4];
#pragma unroll
    for (int mt = 0; mt < 2; mt++)
#pragma unroll
        for (int nt = 0; nt < 8; nt++)
#pragma unroll
            for (int e = 0; e < 4; e++) acc[mt][nt][e] = 0.f;

    auto load = [&](int c, int st) {
        int seg = c >> 2, w = c & 3;
        int aoff = ((seg == 1) ? 256 : 0) + w * 64;  // eh, em, eh
        int boff = ((seg == 2) ? 256 : 0) + w * 64;  // wh, wh, wm
#pragma unroll
        for (int t = 0; t < 2; t++) {
            int uu = tid + t * 512;
            int row = uu >> 3, q8 = uu & 7;
            const void* src = &g_Eh[(size_t)idxS[row] * 512 + aoff + q8 * 8];
            int bo = row * 128 + q8 * 16;
            CPASYNC16(sb + ESA(st) + (uint32_t)(bo ^ ((row & 7) << 4)), src);
        }
#pragma unroll
        for (int t = 0; t < 4; t++) {
            int uu = tid + t * 512;
            int row = uu >> 3, q8 = uu & 7;
            const void* src = Bbase + (size_t)row * 512 + boff + q8 * 8;
            int bo = row * 128 + q8 * 16;
            CPASYNC16(sb + ESB(st) + (uint32_t)(bo ^ ((row & 7) << 4)), src);
        }
        CPCOMMIT();
    };

    load(0, 0);
    load(1, 1);
    for (int cc = 0; cc < 4; cc++) {
#pragma unroll
        for (int s3 = 0; s3 < 3; s3++) {
            int c = cc * 3 + s3;
            if (c < 11) CPWAIT1(); else CPWAIT0();
            __syncthreads();
            if (c + 2 < 12) load(c + 2, (s3 + 2) % 3);
#pragma unroll
            for (int ks = 0; ks < 4; ks++) {
                uint32_t a[2][4];
#pragma unroll
                for (int mt = 0; mt < 2; mt++)
                    ldsm_x4(a[mt][0], a[mt][1], a[mt][2], a[mt][3],
                            sb + ESA(s3) + aRow + mt * 2048 + (((uint32_t)(ks * 32) + aKq) ^ swz));
                uint32_t b[8][2];
#pragma unroll
                for (int p = 0; p < 4; p++)
                    ldsm_x4(b[2 * p][0], b[2 * p][1], b[2 * p + 1][0], b[2 * p + 1][1],
                            sb + ESB(s3) + bRow + p * 2048 + (((uint32_t)(ks * 32) + bKq) ^ swz));
#pragma unroll
                for (int mt = 0; mt < 2; mt++)
#pragma unroll
                    for (int nt = 0; nt < 8; nt++)
                        mma16816(acc[mt][nt], a[mt], b[nt]);
            }
        }
    }

#pragma unroll
    for (int nt = 0; nt < 8; nt++) {
        int col = ncol0 + wn * 64 + nt * 8 + 2 * (lane & 3);
        float b0 = __ldg(&bias[col]), b1 = __ldg(&bias[col + 1]);
#pragma unroll
        for (int mt = 0; mt < 2; mt++) {
#pragma unroll
            for (int key = 0; key < 2; key++) {
                int tok = tok0 + wm * 32 + mt * 16 + key * 8 + (lane >> 2);
                if (tok < M_TOK) {
                    float2 o = {acc[mt][nt][key * 2 + 0] + b0, acc[mt][nt][key * 2 + 1] + b1};
                    *(float2*)&out[(size_t)tok * CIN + col] = o;
                }
            }
        }
    }
}

// ===================== loss partials =====================
__global__ void k_loss(const float* __restrict__ E) {
    __shared__ int idxS[64];
    __shared__ float red[256];
    int row0 = blockIdx.x * 64;
    if (threadIdx.x < 64) idxS[threadIdx.x] = g_idx[row0 + threadIdx.x];
    __syncthreads();
    float s = 0.f;
    for (int idx = threadIdx.x; idx < 64 * CD; idx += 256) {
        int r = idx >> 8, k = idx & 255;
        float d = E[(size_t)idxS[r] * CD + k] - g_zf[(size_t)(row0 + r) * CD + k];
        s += d * d;
    }
    red[threadIdx.x] = s;
    __syncthreads();
    for (int off = 128; off > 0; off >>= 1) {
        if (threadIdx.x < off) red[threadIdx.x] += red[threadIdx.x + off];
        __syncthreads();
    }
    if (threadIdx.x == 0) g_lpart[blockIdx.x] = red[0];
}

__global__ void k_final(float* out_loss) {
    __shared__ float red[256];
    float s = (threadIdx.x < M_TOK / 64) ? g_lpart[threadIdx.x] : 0.f;
    red[threadIdx.x] = s;
    __syncthreads();
    for (int off = 128; off > 0; off >>= 1) {
        if (threadIdx.x < off) red[threadIdx.x] += red[threadIdx.x + off];
        __syncthreads();
    }
    if (threadIdx.x == 0) out_loss[0] = 3.0f * red[0] / (float)((size_t)M_TOK * CD);
}

extern "C" void kernel_launch(void* const* d_in, const int* in_sizes, int n_in,
                              void* d_out, int out_size) {
    const float* z   = (const float*)d_in[0];
    const float* emb = (const float*)d_in[1];
    const float* Wc  = (const float*)d_in[2];
    const float* bc  = (const float*)d_in[3];
    const float* We  = (const float*)d_in[4];
    const float* be  = (const float*)d_in[5];
    float* out = (float*)d_out;

    cudaFuncSetAttribute(k_compressH, cudaFuncAttributeMaxDynamicSharedMemorySize, SMEM_CMP);
    cudaFuncSetAttribute(k_dist, cudaFuncAttributeMaxDynamicSharedMemorySize, SMEM_DIST);
    cudaFuncSetAttribute(k_expand, cudaFuncAttributeMaxDynamicSharedMemorySize, SMEM_EXP);

    k_prepE<<<NE, 256>>>(emb);
    k_splitWt<<<dim3(8, 24), dim3(32, 8)>>>(We);
    k_splitWc<<<dim3(24, 8), dim3(32, 8)>>>(Wc);
    k_splitZin<<<M_PAD, 256>>>(z);
    k_compressH<<<M_PAD / 128, 512, SMEM_CMP>>>(bc);
    k_dist<<<296, 256, SMEM_DIST>>>();
    k_pick<<<(M_TOK + 255) / 256, 256>>>();
    k_expand<<<NUEXP, 512, SMEM_EXP>>>(be, out);
    k_loss<<<M_TOK / 64, 256>>>(emb);
    if (out_size > M_TOK * CIN) k_final<<<1, 256>>>(out + (size_t)M_TOK * CIN);
}